// round 1
// baseline (speedup 1.0000x reference)
#include <cuda_runtime.h>

namespace {

constexpr int ATOM   = 34;
constexpr int HID    = 256;
constexpr int LATENT = 128;
constexpr int CELLS  = 512;
constexpr int NN     = 128;            // nodes per graph
constexpr int DIN    = LATENT + CELLS; // 640
constexpr int NTHR   = 512;
constexpr int NWARP  = 16;
constexpr float NEGV = -9e15f;

struct __align__(16) Smem {
    alignas(16) float Wg[3][ATOM][ATOM];
    float bg[3][ATOM];
    float attnv[3][2 * ATOM];
    alignas(16) float Wt[ATOM][HID];
    float bt[HID];
    alignas(16) float Wf[HID][ATOM];
    alignas(16) float Wfc32[HID];
    alignas(16) float Wfc33[HID];
    float bf[ATOM];
    alignas(16) float Wf2[ATOM][LATENT];
    alignas(16) float bf2[LATENT];
    alignas(16) float x[NN][35];
    float xs0[NN][ATOM];
    alignas(16) float h[NN][35];
    float fsrc[NN];
    float fdst[NN];
    alignas(16) float attbuf[NWARP][NN][4];
    float gbuf[NWARP][HID];
    float dvbuf[NWARP][36];
    float wmax[NWARP][LATENT];
    float vec[DIN];
    float h1[128];
    float h2[256];
    float h3[512];
    float red[NWARP];
};

__device__ __forceinline__ float warp_max(float v) {
    #pragma unroll
    for (int off = 16; off; off >>= 1)
        v = fmaxf(v, __shfl_xor_sync(0xffffffffu, v, off));
    return v;
}
__device__ __forceinline__ float warp_sum(float v) {
    #pragma unroll
    for (int off = 16; off; off >>= 1)
        v += __shfl_xor_sync(0xffffffffu, v, off);
    return v;
}

__global__ void __launch_bounds__(NTHR, 1)
disease_kernel(const float* __restrict__ xs, const int* __restrict__ A,
               const float* __restrict__ cell,
               const float* __restrict__ Wg_g, const float* __restrict__ bg_g,
               const float* __restrict__ attn_g,
               const float* __restrict__ Wt_g, const float* __restrict__ bt_g,
               const float* __restrict__ Wf_g, const float* __restrict__ bf_g,
               const float* __restrict__ Wf2_g, const float* __restrict__ bf2_g,
               const float* __restrict__ W1, const float* __restrict__ b1,
               const float* __restrict__ W2, const float* __restrict__ b2,
               const float* __restrict__ W3, const float* __restrict__ b3,
               const float* __restrict__ W4, const float* __restrict__ b4,
               float* __restrict__ out)
{
    extern __shared__ char smem_raw[];
    Smem& s = *reinterpret_cast<Smem*>(smem_raw);
    const int b    = blockIdx.x;
    const int tid  = threadIdx.x;
    const int lane = tid & 31;
    const int w    = tid >> 5;

    // ---------- stage weights + inputs into smem ----------
    for (int i = tid; i < 3 * ATOM * ATOM; i += NTHR) (&s.Wg[0][0][0])[i] = Wg_g[i];
    for (int i = tid; i < 3 * ATOM; i += NTHR)        (&s.bg[0][0])[i]    = bg_g[i];
    for (int i = tid; i < 3 * 2 * ATOM; i += NTHR)    (&s.attnv[0][0])[i] = attn_g[i];
    for (int i = tid; i < ATOM * HID; i += NTHR)      (&s.Wt[0][0])[i]    = Wt_g[i];
    for (int i = tid; i < HID; i += NTHR)             s.bt[i]             = bt_g[i];
    for (int i = tid; i < HID * ATOM; i += NTHR)      (&s.Wf[0][0])[i]    = Wf_g[i];
    for (int i = tid; i < HID; i += NTHR) {
        s.Wfc32[i] = Wf_g[i * ATOM + 32];
        s.Wfc33[i] = Wf_g[i * ATOM + 33];
    }
    for (int i = tid; i < ATOM; i += NTHR)            s.bf[i]             = bf_g[i];
    for (int i = tid; i < ATOM * LATENT; i += NTHR)   (&s.Wf2[0][0])[i]   = Wf2_g[i];
    for (int i = tid; i < LATENT; i += NTHR)          s.bf2[i]            = bf2_g[i];
    for (int i = tid; i < NN * ATOM; i += NTHR) {
        int n = i / ATOM, d = i % ATOM;
        float v = xs[((size_t)b * NN + n) * ATOM + d];
        s.x[n][d]  = v;
        s.xs0[n][d] = v;
    }
    __syncthreads();

    const int* __restrict__ Abase = A + (size_t)b * NN * NN;

    // ---------- 3 GAT rounds ----------
    for (int r = 0; r < 3; r++) {
        // h = relu(x @ Wg[r] + bg[r])
        for (int i = tid; i < NN * ATOM; i += NTHR) {
            int n = i / ATOM, e = i % ATOM;
            float acc = s.bg[r][e];
            #pragma unroll
            for (int d = 0; d < ATOM; d++) acc += s.x[n][d] * s.Wg[r][d][e];
            s.h[n][e] = fmaxf(acc, 0.f);
        }
        __syncthreads();
        if (tid < NN) {
            const int n = tid;
            float a0 = 0.f, a1 = 0.f;
            #pragma unroll
            for (int e = 0; e < ATOM; e++) {
                float hv = s.h[n][e];
                a0 += hv * s.attnv[r][e];
                a1 += hv * s.attnv[r][ATOM + e];
            }
            s.fsrc[n] = a0;
            s.fdst[n] = a1;
        }
        __syncthreads();

        #pragma unroll
        for (int pass = 0; pass < 2; pass++) {
            const int p0 = w + 64 * pass;   // rows p0 + 16*rr, rr in 0..3

            // softmax weights (4 rows per warp)
            #pragma unroll
            for (int rr = 0; rr < 4; rr++) {
                const int p = p0 + 16 * rr;
                const float fs = s.fsrc[p];
                const int* __restrict__ Ar = Abase + p * NN;
                float sc[4];
                #pragma unroll
                for (int j = 0; j < 4; j++) {
                    int q = lane + 32 * j;
                    float e = fs + s.fdst[q];
                    e = e > 0.f ? e : 0.01f * e;           // leaky_relu(0.01)
                    sc[j] = (Ar[q] > 0) ? e : NEGV;        // mask
                }
                float m = warp_max(fmaxf(fmaxf(sc[0], sc[1]), fmaxf(sc[2], sc[3])));
                float wv[4], sum = 0.f;
                #pragma unroll
                for (int j = 0; j < 4; j++) { wv[j] = __expf(sc[j] - m); sum += wv[j]; }
                sum = warp_sum(sum);
                const float inv = 1.f / sum;
                #pragma unroll
                for (int j = 0; j < 4; j++) s.attbuf[w][lane + 32 * j][rr] = wv[j] * inv;
            }
            __syncwarp();

            // msg[d=lane] = sum_q att[q] * h[q][lane]
            float m0[4] = {0.f, 0.f, 0.f, 0.f};
            #pragma unroll 4
            for (int q = 0; q < NN; q++) {
                float hv = s.h[q][lane];
                float4 a = *reinterpret_cast<const float4*>(&s.attbuf[w][q][0]);
                m0[0] += a.x * hv;
                m0[1] += a.y * hv;
                m0[2] += a.z * hv;
                m0[3] += a.w * hv;
            }
            // dims 32,33 via lane-partitioned partials
            float m32[4] = {0.f, 0.f, 0.f, 0.f}, m33[4] = {0.f, 0.f, 0.f, 0.f};
            #pragma unroll
            for (int j = 0; j < 4; j++) {
                int q = lane + 32 * j;
                float h32 = s.h[q][32], h33 = s.h[q][33];
                float4 a = *reinterpret_cast<const float4*>(&s.attbuf[w][q][0]);
                m32[0] += a.x * h32; m32[1] += a.y * h32; m32[2] += a.z * h32; m32[3] += a.w * h32;
                m33[0] += a.x * h33; m33[1] += a.y * h33; m33[2] += a.z * h33; m33[3] += a.w * h33;
            }
            #pragma unroll
            for (int rr = 0; rr < 4; rr++) { m32[rr] = warp_sum(m32[rr]); m33[rr] = warp_sum(m33[rr]); }
            #pragma unroll
            for (int rr = 0; rr < 4; rr++) {
                const int p = p0 + 16 * rr;
                s.x[p][lane] += m0[rr];
                if (lane == 0) {
                    s.x[p][32] += m32[rr];
                    s.x[p][33] += m33[rr];
                }
            }
            __syncwarp();
        }
        __syncthreads();
    }

    // ---------- readout: g = relu(x@Wt+bt); d = g@Wf+bf+xs0; lat = d@Wf2+bf2; rowmax ----------
    float rmax[4] = {-3.4e38f, -3.4e38f, -3.4e38f, -3.4e38f};
    for (int n = w; n < NN; n += NWARP) {
        float g0[8];
        const int e0 = 8 * lane;
        {
            #pragma unroll
            for (int j = 0; j < 8; j++) g0[j] = s.bt[e0 + j];
            #pragma unroll 2
            for (int d = 0; d < ATOM; d++) {
                float xv = s.x[n][d];
                float4 w0 = *reinterpret_cast<const float4*>(&s.Wt[d][e0]);
                float4 w1 = *reinterpret_cast<const float4*>(&s.Wt[d][e0 + 4]);
                g0[0] += xv * w0.x; g0[1] += xv * w0.y; g0[2] += xv * w0.z; g0[3] += xv * w0.w;
                g0[4] += xv * w1.x; g0[5] += xv * w1.y; g0[6] += xv * w1.z; g0[7] += xv * w1.w;
            }
            #pragma unroll
            for (int j = 0; j < 8; j++) { g0[j] = fmaxf(g0[j], 0.f); s.gbuf[w][e0 + j] = g0[j]; }
        }
        __syncwarp();

        // d[lane] over 256 hidden (4 independent chains)
        float dvp0 = 0.f, dvp1 = 0.f, dvp2 = 0.f, dvp3 = 0.f;
        #pragma unroll 4
        for (int e = 0; e < HID; e += 4) {
            dvp0 += s.gbuf[w][e]     * s.Wf[e][lane];
            dvp1 += s.gbuf[w][e + 1] * s.Wf[e + 1][lane];
            dvp2 += s.gbuf[w][e + 2] * s.Wf[e + 2][lane];
            dvp3 += s.gbuf[w][e + 3] * s.Wf[e + 3][lane];
        }
        float dv = s.bf[lane] + s.xs0[n][lane] + (dvp0 + dvp1) + (dvp2 + dvp3);

        // d[32], d[33] via partials over this lane's register g chunk
        float p32, p33;
        {
            float4 c32a = *reinterpret_cast<const float4*>(&s.Wfc32[e0]);
            float4 c32b = *reinterpret_cast<const float4*>(&s.Wfc32[e0 + 4]);
            float4 c33a = *reinterpret_cast<const float4*>(&s.Wfc33[e0]);
            float4 c33b = *reinterpret_cast<const float4*>(&s.Wfc33[e0 + 4]);
            p32 = g0[0]*c32a.x + g0[1]*c32a.y + g0[2]*c32a.z + g0[3]*c32a.w
                + g0[4]*c32b.x + g0[5]*c32b.y + g0[6]*c32b.z + g0[7]*c32b.w;
            p33 = g0[0]*c33a.x + g0[1]*c33a.y + g0[2]*c33a.z + g0[3]*c33a.w
                + g0[4]*c33b.x + g0[5]*c33b.y + g0[6]*c33b.z + g0[7]*c33b.w;
        }
        p32 = warp_sum(p32);
        p33 = warp_sum(p33);
        s.dvbuf[w][lane] = dv;
        if (lane == 0) {
            s.dvbuf[w][32] = p32 + s.bf[32] + s.xs0[n][32];
            s.dvbuf[w][33] = p33 + s.bf[33] + s.xs0[n][33];
        }
        __syncwarp();

        // latent: l = 4*lane .. 4*lane+3
        {
            const int l0 = 4 * lane;
            float4 acc = *reinterpret_cast<const float4*>(&s.bf2[l0]);
            #pragma unroll 2
            for (int d = 0; d < ATOM; d++) {
                float dvd = s.dvbuf[w][d];
                float4 wv = *reinterpret_cast<const float4*>(&s.Wf2[d][l0]);
                acc.x += dvd * wv.x; acc.y += dvd * wv.y; acc.z += dvd * wv.z; acc.w += dvd * wv.w;
            }
            rmax[0] = fmaxf(rmax[0], acc.x);
            rmax[1] = fmaxf(rmax[1], acc.y);
            rmax[2] = fmaxf(rmax[2], acc.z);
            rmax[3] = fmaxf(rmax[3], acc.w);
        }
        __syncwarp();
    }
    #pragma unroll
    for (int j = 0; j < 4; j++) s.wmax[w][4 * lane + j] = rmax[j];
    __syncthreads();

    // ---------- vec = sigmoid(concat(max_n lat, cell_emb)) ----------
    if (tid < LATENT) {
        float m = s.wmax[0][tid];
        #pragma unroll
        for (int ww = 1; ww < NWARP; ww++) m = fmaxf(m, s.wmax[ww][tid]);
        s.vec[tid] = 1.f / (1.f + __expf(-m));
    }
    for (int j = tid; j < CELLS; j += NTHR) {
        float c = cell[(size_t)b * CELLS + j];
        s.vec[LATENT + j] = 1.f / (1.f + __expf(-c));
    }
    __syncthreads();

    // ---------- MLP layer 1: 640 -> 128 (4 k-partials per output) ----------
    {
        const int o = tid & 127, part = tid >> 7;
        const int k0 = part * 160;
        float a0 = 0.f, a1 = 0.f, a2 = 0.f, a3 = 0.f;
        #pragma unroll 4
        for (int k = k0; k < k0 + 160; k += 4) {
            a0 += s.vec[k]     * W1[(k)     * 128 + o];
            a1 += s.vec[k + 1] * W1[(k + 1) * 128 + o];
            a2 += s.vec[k + 2] * W1[(k + 2) * 128 + o];
            a3 += s.vec[k + 3] * W1[(k + 3) * 128 + o];
        }
        s.wmax[part][o] = (a0 + a1) + (a2 + a3);
    }
    __syncthreads();
    if (tid < 128) {
        float v = b1[tid] + s.wmax[0][tid] + s.wmax[1][tid] + s.wmax[2][tid] + s.wmax[3][tid];
        s.h1[tid] = fmaxf(v, 0.f);
    }
    __syncthreads();

    // ---------- MLP layer 2: 128 -> 256 (2 k-partials per output) ----------
    {
        const int o = tid & 255, part = tid >> 8;
        const int k0 = part * 64;
        float a0 = 0.f, a1 = 0.f, a2 = 0.f, a3 = 0.f;
        #pragma unroll 4
        for (int k = k0; k < k0 + 64; k += 4) {
            a0 += s.h1[k]     * W2[(k)     * 256 + o];
            a1 += s.h1[k + 1] * W2[(k + 1) * 256 + o];
            a2 += s.h1[k + 2] * W2[(k + 2) * 256 + o];
            a3 += s.h1[k + 3] * W2[(k + 3) * 256 + o];
        }
        (&s.wmax[0][0])[tid] = (a0 + a1) + (a2 + a3);
    }
    __syncthreads();
    if (tid < 256) {
        float v = b2[tid] + (&s.wmax[0][0])[tid] + (&s.wmax[0][0])[tid + 256];
        s.h2[tid] = fmaxf(v, 0.f);
    }
    __syncthreads();

    // ---------- MLP layer 3: 256 -> 512 ----------
    {
        float a0 = 0.f, a1 = 0.f, a2 = 0.f, a3 = 0.f;
        #pragma unroll 4
        for (int k = 0; k < 256; k += 4) {
            a0 += s.h2[k]     * W3[(k)     * 512 + tid];
            a1 += s.h2[k + 1] * W3[(k + 1) * 512 + tid];
            a2 += s.h2[k + 2] * W3[(k + 2) * 512 + tid];
            a3 += s.h2[k + 3] * W3[(k + 3) * 512 + tid];
        }
        s.h3[tid] = fmaxf(b3[tid] + (a0 + a1) + (a2 + a3), 0.f);
    }
    __syncthreads();

    // ---------- MLP layer 4: 512 -> 1 ----------
    {
        float acc = s.h3[tid] * W4[tid];
        acc = warp_sum(acc);
        if (lane == 0) s.red[w] = acc;
    }
    __syncthreads();
    if (tid == 0) {
        float acc = b4[0];
        #pragma unroll
        for (int ww = 0; ww < NWARP; ww++) acc += s.red[ww];
        out[b] = acc;
    }
}

} // namespace

extern "C" void kernel_launch(void* const* d_in, const int* in_sizes, int n_in,
                              void* d_out, int out_size) {
    (void)in_sizes; (void)n_in; (void)out_size;
    const float* xs   = (const float*)d_in[0];
    const int*   A    = (const int*)d_in[1];
    const float* cell = (const float*)d_in[2];
    const float* Wg   = (const float*)d_in[3];
    const float* bg   = (const float*)d_in[4];
    const float* attn = (const float*)d_in[5];
    const float* Wt   = (const float*)d_in[6];
    const float* bt   = (const float*)d_in[7];
    const float* Wf   = (const float*)d_in[8];
    const float* bf   = (const float*)d_in[9];
    const float* Wf2  = (const float*)d_in[10];
    const float* bf2  = (const float*)d_in[11];
    const float* W1   = (const float*)d_in[12];
    const float* b1   = (const float*)d_in[13];
    const float* W2   = (const float*)d_in[14];
    const float* b2   = (const float*)d_in[15];
    const float* W3   = (const float*)d_in[16];
    const float* b3   = (const float*)d_in[17];
    const float* W4   = (const float*)d_in[18];
    const float* b4   = (const float*)d_in[19];
    float* out = (float*)d_out;

    cudaFuncSetAttribute(disease_kernel,
                         cudaFuncAttributeMaxDynamicSharedMemorySize,
                         (int)sizeof(Smem));
    disease_kernel<<<64, NTHR, sizeof(Smem)>>>(
        xs, A, cell, Wg, bg, attn, Wt, bt, Wf, bf, Wf2, bf2,
        W1, b1, W2, b2, W3, b3, W4, b4, out);
}

// round 3
// speedup vs baseline: 1.5198x; 1.5198x over previous
#include <cuda_runtime.h>

namespace {

constexpr int ATOM   = 34;
constexpr int HID    = 256;
constexpr int LATENT = 128;
constexpr int CELLS  = 512;
constexpr int NN     = 128;            // nodes per graph
constexpr int HALF   = 64;             // rows per CTA (cluster of 2)
constexpr int DIN    = LATENT + CELLS; // 640
constexpr int NTHR   = 512;
constexpr int NWARP  = 16;
constexpr float NEGV = -9e15f;

struct __align__(16) Smem {
    alignas(16) float Wg[3][ATOM][ATOM];
    float bg[3][ATOM];
    float attnv[3][2 * ATOM];
    alignas(16) float Wt[ATOM][HID];
    float bt[HID];
    alignas(16) float Wf[HID][ATOM];
    alignas(16) float Wfc32[HID];
    alignas(16) float Wfc33[HID];
    float bf[ATOM];
    alignas(16) float Wf2[ATOM][LATENT];
    alignas(16) float bf2[LATENT];
    alignas(16) float x[NN][35];
    float xs0[HALF][ATOM];
    alignas(16) float h[NN][35];
    float fsrc[NN];
    float fdst[NN];
    unsigned mask[HALF][4];            // adjacency bitmask, own rows only
    alignas(16) float attbuf[NWARP][NN][4];
    float gbuf[NWARP][HID];
    float dvbuf[NWARP][36];
    float wmax[NWARP][LATENT];         // also reused as MLP partial buffer
    float latloc[LATENT];
    float latpeer[LATENT];
    float vec[DIN];
    float h1[128];
    float h2[256];
    float h3own[256];
    float red[NWARP];
    float partial4;                    // written ONLY by peer CTA (rank1 -> rank0)
};

__device__ __forceinline__ float warp_max(float v) {
    #pragma unroll
    for (int off = 16; off; off >>= 1)
        v = fmaxf(v, __shfl_xor_sync(0xffffffffu, v, off));
    return v;
}
__device__ __forceinline__ float warp_sum(float v) {
    #pragma unroll
    for (int off = 16; off; off >>= 1)
        v += __shfl_xor_sync(0xffffffffu, v, off);
    return v;
}
__device__ __forceinline__ unsigned smem_u32(const void* p) {
    return (unsigned)__cvta_generic_to_shared(p);
}
__device__ __forceinline__ unsigned mapa_peer(unsigned local, unsigned rank) {
    unsigned r;
    asm("mapa.shared::cluster.u32 %0, %1, %2;" : "=r"(r) : "r"(local), "r"(rank));
    return r;
}
__device__ __forceinline__ void st_cluster_f32(unsigned addr, float v) {
    asm volatile("st.shared::cluster.f32 [%0], %1;" :: "r"(addr), "f"(v) : "memory");
}
__device__ __forceinline__ void cluster_sync_() {
    asm volatile("barrier.cluster.arrive.aligned;" ::: "memory");
    asm volatile("barrier.cluster.wait.aligned;" ::: "memory");
}
__device__ __forceinline__ unsigned ctarank() {
    unsigned r;
    asm("mov.u32 %0, %%cluster_ctarank;" : "=r"(r));
    return r;
}

__global__ void __launch_bounds__(NTHR, 1) __cluster_dims__(2, 1, 1)
disease_kernel(const float* __restrict__ xs, const int* __restrict__ A,
               const float* __restrict__ cell,
               const float* __restrict__ Wg_g, const float* __restrict__ bg_g,
               const float* __restrict__ attn_g,
               const float* __restrict__ Wt_g, const float* __restrict__ bt_g,
               const float* __restrict__ Wf_g, const float* __restrict__ bf_g,
               const float* __restrict__ Wf2_g, const float* __restrict__ bf2_g,
               const float* __restrict__ W1, const float* __restrict__ b1,
               const float* __restrict__ W2, const float* __restrict__ b2,
               const float* __restrict__ W3, const float* __restrict__ b3,
               const float* __restrict__ W4, const float* __restrict__ b4,
               float* __restrict__ out)
{
    extern __shared__ char smem_raw[];
    Smem& s = *reinterpret_cast<Smem*>(smem_raw);
    const int b     = blockIdx.x >> 1;
    const unsigned rank = ctarank();
    const unsigned prk  = rank ^ 1u;
    const int own0  = (int)rank * HALF;
    const int tid   = threadIdx.x;
    const int lane  = tid & 31;
    const int w     = tid >> 5;

    const unsigned peer_x   = mapa_peer(smem_u32(&s.x[0][0]), prk);
    const unsigned peer_lat = mapa_peer(smem_u32(&s.latpeer[0]), prk);

    // ---------- stage weights + inputs into smem ----------
    for (int i = tid; i < 3 * ATOM * ATOM; i += NTHR) (&s.Wg[0][0][0])[i] = Wg_g[i];
    for (int i = tid; i < 3 * ATOM; i += NTHR)        (&s.bg[0][0])[i]    = bg_g[i];
    for (int i = tid; i < 3 * 2 * ATOM; i += NTHR)    (&s.attnv[0][0])[i] = attn_g[i];
    for (int i = tid; i < ATOM * HID; i += NTHR)      (&s.Wt[0][0])[i]    = Wt_g[i];
    for (int i = tid; i < HID; i += NTHR)             s.bt[i]             = bt_g[i];
    for (int i = tid; i < HID * ATOM; i += NTHR)      (&s.Wf[0][0])[i]    = Wf_g[i];
    for (int i = tid; i < HID; i += NTHR) {
        s.Wfc32[i] = Wf_g[i * ATOM + 32];
        s.Wfc33[i] = Wf_g[i * ATOM + 33];
    }
    for (int i = tid; i < ATOM; i += NTHR)            s.bf[i]             = bf_g[i];
    for (int i = tid; i < ATOM * LATENT; i += NTHR)   (&s.Wf2[0][0])[i]   = Wf2_g[i];
    for (int i = tid; i < LATENT; i += NTHR)          s.bf2[i]            = bf2_g[i];
    for (int i = tid; i < NN * ATOM; i += NTHR) {
        int n = i / ATOM, d = i % ATOM;
        float v = xs[((size_t)b * NN + n) * ATOM + d];
        s.x[n][d] = v;
        if (n >= own0 && n < own0 + HALF) s.xs0[n - own0][d] = v;
    }

    // ---------- adjacency bitmask (own 64 rows), built once via ballot ----------
    {
        const int* __restrict__ Abase = A + (size_t)b * NN * NN;
        #pragma unroll
        for (int t = 0; t < 16; t++) {
            int widx  = w * 16 + t;            // 0..255
            int row   = widx >> 2;             // local row
            int chunk = widx & 3;
            int q     = chunk * 32 + lane;
            int av    = Abase[(own0 + row) * NN + q];
            unsigned word = __ballot_sync(0xffffffffu, av > 0);
            if (lane == 0) s.mask[row][chunk] = word;
        }
    }
    __syncthreads();

    // ---------- 3 GAT rounds (rows split across the 2-CTA cluster) ----------
    for (int r = 0; r < 3; r++) {
        // h = relu(x @ Wg[r] + bg[r])  (full, duplicated per CTA)
        for (int i = tid; i < NN * ATOM; i += NTHR) {
            int n = i / ATOM, e = i % ATOM;
            float acc = s.bg[r][e];
            #pragma unroll
            for (int d = 0; d < ATOM; d++) acc += s.x[n][d] * s.Wg[r][d][e];
            s.h[n][e] = fmaxf(acc, 0.f);
        }
        __syncthreads();
        if (tid < NN) {
            const int n = tid;
            float a0 = 0.f, a1 = 0.f;
            #pragma unroll
            for (int e = 0; e < ATOM; e++) {
                float hv = s.h[n][e];
                a0 += hv * s.attnv[r][e];
                a1 += hv * s.attnv[r][ATOM + e];
            }
            s.fsrc[n] = a0;
            s.fdst[n] = a1;
        }
        // all x reads for this round are done -> safe for peer to overwrite x rows
        cluster_sync_();

        // softmax weights: 4 own rows per warp (p = own0 + w + 16*rr)
        #pragma unroll
        for (int rr = 0; rr < 4; rr++) {
            const int p = own0 + w + 16 * rr;
            const float fs = s.fsrc[p];
            float sc[4];
            #pragma unroll
            for (int j = 0; j < 4; j++) {
                int q = lane + 32 * j;
                float e = fs + s.fdst[q];
                e = e > 0.f ? e : 0.01f * e;                     // leaky_relu(0.01)
                bool on = (s.mask[p - own0][j] >> lane) & 1u;
                sc[j] = on ? e : NEGV;
            }
            float m = warp_max(fmaxf(fmaxf(sc[0], sc[1]), fmaxf(sc[2], sc[3])));
            float wv[4], sum = 0.f;
            #pragma unroll
            for (int j = 0; j < 4; j++) { wv[j] = __expf(sc[j] - m); sum += wv[j]; }
            sum = warp_sum(sum);
            const float inv = 1.f / sum;
            #pragma unroll
            for (int j = 0; j < 4; j++) s.attbuf[w][lane + 32 * j][rr] = wv[j] * inv;
        }
        __syncwarp();

        // msg[d=lane] = sum_q att[q] * h[q][lane]
        float m0[4] = {0.f, 0.f, 0.f, 0.f};
        #pragma unroll 4
        for (int q = 0; q < NN; q++) {
            float hv = s.h[q][lane];
            float4 a = *reinterpret_cast<const float4*>(&s.attbuf[w][q][0]);
            m0[0] += a.x * hv;
            m0[1] += a.y * hv;
            m0[2] += a.z * hv;
            m0[3] += a.w * hv;
        }
        float m32[4] = {0.f, 0.f, 0.f, 0.f}, m33[4] = {0.f, 0.f, 0.f, 0.f};
        #pragma unroll
        for (int j = 0; j < 4; j++) {
            int q = lane + 32 * j;
            float h32 = s.h[q][32], h33 = s.h[q][33];
            float4 a = *reinterpret_cast<const float4*>(&s.attbuf[w][q][0]);
            m32[0] += a.x * h32; m32[1] += a.y * h32; m32[2] += a.z * h32; m32[3] += a.w * h32;
            m33[0] += a.x * h33; m33[1] += a.y * h33; m33[2] += a.z * h33; m33[3] += a.w * h33;
        }
        #pragma unroll
        for (int rr = 0; rr < 4; rr++) { m32[rr] = warp_sum(m32[rr]); m33[rr] = warp_sum(m33[rr]); }
        #pragma unroll
        for (int rr = 0; rr < 4; rr++) {
            const int p = own0 + w + 16 * rr;
            float nv = s.x[p][lane] + m0[rr];
            s.x[p][lane] = nv;
            st_cluster_f32(peer_x + (unsigned)(p * 35 + lane) * 4u, nv);
            if (lane == 0) {
                float nv32 = s.x[p][32] + m32[rr];
                float nv33 = s.x[p][33] + m33[rr];
                s.x[p][32] = nv32;
                s.x[p][33] = nv33;
                st_cluster_f32(peer_x + (unsigned)(p * 35 + 32) * 4u, nv32);
                st_cluster_f32(peer_x + (unsigned)(p * 35 + 33) * 4u, nv33);
            }
        }
        // x updates (local + peer) visible to everyone
        cluster_sync_();
    }

    // ---------- readout over own 64 rows ----------
    float rmax[4] = {-3.4e38f, -3.4e38f, -3.4e38f, -3.4e38f};
    for (int n = own0 + w; n < own0 + HALF; n += NWARP) {
        float g0[8];
        const int e0 = 8 * lane;
        {
            #pragma unroll
            for (int j = 0; j < 8; j++) g0[j] = s.bt[e0 + j];
            #pragma unroll 2
            for (int d = 0; d < ATOM; d++) {
                float xv = s.x[n][d];
                float4 w0 = *reinterpret_cast<const float4*>(&s.Wt[d][e0]);
                float4 w1 = *reinterpret_cast<const float4*>(&s.Wt[d][e0 + 4]);
                g0[0] += xv * w0.x; g0[1] += xv * w0.y; g0[2] += xv * w0.z; g0[3] += xv * w0.w;
                g0[4] += xv * w1.x; g0[5] += xv * w1.y; g0[6] += xv * w1.z; g0[7] += xv * w1.w;
            }
            #pragma unroll
            for (int j = 0; j < 8; j++) { g0[j] = fmaxf(g0[j], 0.f); s.gbuf[w][e0 + j] = g0[j]; }
        }
        __syncwarp();

        float dvp0 = 0.f, dvp1 = 0.f, dvp2 = 0.f, dvp3 = 0.f;
        #pragma unroll 4
        for (int e = 0; e < HID; e += 4) {
            dvp0 += s.gbuf[w][e]     * s.Wf[e][lane];
            dvp1 += s.gbuf[w][e + 1] * s.Wf[e + 1][lane];
            dvp2 += s.gbuf[w][e + 2] * s.Wf[e + 2][lane];
            dvp3 += s.gbuf[w][e + 3] * s.Wf[e + 3][lane];
        }
        float dv = s.bf[lane] + s.xs0[n - own0][lane] + (dvp0 + dvp1) + (dvp2 + dvp3);

        float p32, p33;
        {
            float4 c32a = *reinterpret_cast<const float4*>(&s.Wfc32[e0]);
            float4 c32b = *reinterpret_cast<const float4*>(&s.Wfc32[e0 + 4]);
            float4 c33a = *reinterpret_cast<const float4*>(&s.Wfc33[e0]);
            float4 c33b = *reinterpret_cast<const float4*>(&s.Wfc33[e0 + 4]);
            p32 = g0[0]*c32a.x + g0[1]*c32a.y + g0[2]*c32a.z + g0[3]*c32a.w
                + g0[4]*c32b.x + g0[5]*c32b.y + g0[6]*c32b.z + g0[7]*c32b.w;
            p33 = g0[0]*c33a.x + g0[1]*c33a.y + g0[2]*c33a.z + g0[3]*c33a.w
                + g0[4]*c33b.x + g0[5]*c33b.y + g0[6]*c33b.z + g0[7]*c33b.w;
        }
        p32 = warp_sum(p32);
        p33 = warp_sum(p33);
        s.dvbuf[w][lane] = dv;
        if (lane == 0) {
            s.dvbuf[w][32] = p32 + s.bf[32] + s.xs0[n - own0][32];
            s.dvbuf[w][33] = p33 + s.bf[33] + s.xs0[n - own0][33];
        }
        __syncwarp();

        {
            const int l0 = 4 * lane;
            float4 acc = *reinterpret_cast<const float4*>(&s.bf2[l0]);
            #pragma unroll 2
            for (int d = 0; d < ATOM; d++) {
                float dvd = s.dvbuf[w][d];
                float4 wv = *reinterpret_cast<const float4*>(&s.Wf2[d][l0]);
                acc.x += dvd * wv.x; acc.y += dvd * wv.y; acc.z += dvd * wv.z; acc.w += dvd * wv.w;
            }
            rmax[0] = fmaxf(rmax[0], acc.x);
            rmax[1] = fmaxf(rmax[1], acc.y);
            rmax[2] = fmaxf(rmax[2], acc.z);
            rmax[3] = fmaxf(rmax[3], acc.w);
        }
        __syncwarp();
    }
    #pragma unroll
    for (int j = 0; j < 4; j++) s.wmax[w][4 * lane + j] = rmax[j];
    __syncthreads();

    // ---------- combine row-max across warps, exchange across cluster ----------
    if (tid < LATENT) {
        float m = s.wmax[0][tid];
        #pragma unroll
        for (int ww = 1; ww < NWARP; ww++) m = fmaxf(m, s.wmax[ww][tid]);
        s.latloc[tid] = m;
        st_cluster_f32(peer_lat + (unsigned)tid * 4u, m);
    }
    cluster_sync_();

    // ---------- vec = sigmoid(concat(max, cell_emb)) (full, per CTA) ----------
    if (tid < LATENT) {
        float m = fmaxf(s.latloc[tid], s.latpeer[tid]);
        s.vec[tid] = 1.f / (1.f + __expf(-m));
    }
    for (int j = tid; j < CELLS; j += NTHR) {
        float c = cell[(size_t)b * CELLS + j];
        s.vec[LATENT + j] = 1.f / (1.f + __expf(-c));
    }
    __syncthreads();

    const unsigned peer_h1 = mapa_peer(smem_u32(&s.h1[0]), prk);
    const unsigned peer_h2 = mapa_peer(smem_u32(&s.h2[0]), prk);
    const unsigned peer_p4 = mapa_peer(smem_u32(&s.partial4), prk);

    // ---------- MLP L1: 640 -> 128, own 64 columns (8 k-partials each) ----------
    {
        const int o = tid & 63, part = tid >> 6;      // 8 parts x 80 k
        const int og = own0 + o;
        const int k0 = part * 80;
        float a0 = 0.f, a1 = 0.f, a2 = 0.f, a3 = 0.f;
        #pragma unroll 4
        for (int k = k0; k < k0 + 80; k += 4) {
            a0 += s.vec[k]     * W1[(k)     * 128 + og];
            a1 += s.vec[k + 1] * W1[(k + 1) * 128 + og];
            a2 += s.vec[k + 2] * W1[(k + 2) * 128 + og];
            a3 += s.vec[k + 3] * W1[(k + 3) * 128 + og];
        }
        (&s.wmax[0][0])[part * 64 + o] = (a0 + a1) + (a2 + a3);
    }
    __syncthreads();
    if (tid < 64) {
        const int og = own0 + tid;
        float v = b1[og];
        #pragma unroll
        for (int p = 0; p < 8; p++) v += (&s.wmax[0][0])[p * 64 + tid];
        v = fmaxf(v, 0.f);
        s.h1[og] = v;
        st_cluster_f32(peer_h1 + (unsigned)og * 4u, v);
    }
    cluster_sync_();

    // ---------- MLP L2: 128 -> 256, own 128 columns (4 k-partials each) ----------
    {
        const int o = tid & 127, part = tid >> 7;     // 4 parts x 32 k
        const int og = (int)rank * 128 + o;
        const int k0 = part * 32;
        float a0 = 0.f, a1 = 0.f, a2 = 0.f, a3 = 0.f;
        #pragma unroll 4
        for (int k = k0; k < k0 + 32; k += 4) {
            a0 += s.h1[k]     * W2[(k)     * 256 + og];
            a1 += s.h1[k + 1] * W2[(k + 1) * 256 + og];
            a2 += s.h1[k + 2] * W2[(k + 2) * 256 + og];
            a3 += s.h1[k + 3] * W2[(k + 3) * 256 + og];
        }
        (&s.wmax[0][0])[part * 128 + o] = (a0 + a1) + (a2 + a3);
    }
    __syncthreads();
    if (tid < 128) {
        const int og = (int)rank * 128 + tid;
        float v = b2[og];
        #pragma unroll
        for (int p = 0; p < 4; p++) v += (&s.wmax[0][0])[p * 128 + tid];
        v = fmaxf(v, 0.f);
        s.h2[og] = v;
        st_cluster_f32(peer_h2 + (unsigned)og * 4u, v);
    }
    cluster_sync_();

    // ---------- MLP L3: 256 -> 512, own 256 columns (2 k-partials each) ----------
    {
        const int o = tid & 255, part = tid >> 8;     // 2 parts x 128 k
        const int og = (int)rank * 256 + o;
        const int k0 = part * 128;
        float a0 = 0.f, a1 = 0.f, a2 = 0.f, a3 = 0.f;
        #pragma unroll 4
        for (int k = k0; k < k0 + 128; k += 4) {
            a0 += s.h2[k]     * W3[(k)     * 512 + og];
            a1 += s.h2[k + 1] * W3[(k + 1) * 512 + og];
            a2 += s.h2[k + 2] * W3[(k + 2) * 512 + og];
            a3 += s.h2[k + 3] * W3[(k + 3) * 512 + og];
        }
        (&s.wmax[0][0])[part * 256 + o] = (a0 + a1) + (a2 + a3);
    }
    __syncthreads();
    if (tid < 256) {
        float v = b3[(int)rank * 256 + tid]
                + (&s.wmax[0][0])[tid] + (&s.wmax[0][0])[256 + tid];
        s.h3own[tid] = fmaxf(v, 0.f);
    }
    __syncthreads();

    // ---------- MLP L4: 512 -> 1, split dot across cluster ----------
    {
        float acc = 0.f;
        if (tid < 256) acc = s.h3own[tid] * W4[(int)rank * 256 + tid];
        acc = warp_sum(acc);
        if (lane == 0) s.red[w] = acc;
    }
    __syncthreads();
    // RACE FIX vs R2: only rank1 writes partial4 (into rank0's smem via DSMEM).
    // rank0 does NOT touch partial4 locally, so there is no same-address race;
    // rank1's release-arrive -> rank0's acquire-wait orders the store.
    if (rank == 1 && tid == 0) {
        float acc = 0.f;
        #pragma unroll
        for (int ww = 0; ww < 8; ww++) acc += s.red[ww];
        st_cluster_f32(peer_p4, acc);
    }
    cluster_sync_();
    if (rank == 0 && tid == 0) {
        float acc = 0.f;
        #pragma unroll
        for (int ww = 0; ww < 8; ww++) acc += s.red[ww];
        out[b] = acc + s.partial4 + b4[0];
    }
}

} // namespace

extern "C" void kernel_launch(void* const* d_in, const int* in_sizes, int n_in,
                              void* d_out, int out_size) {
    (void)in_sizes; (void)n_in; (void)out_size;
    const float* xs   = (const float*)d_in[0];
    const int*   A    = (const int*)d_in[1];
    const float* cell = (const float*)d_in[2];
    const float* Wg   = (const float*)d_in[3];
    const float* bg   = (const float*)d_in[4];
    const float* attn = (const float*)d_in[5];
    const float* Wt   = (const float*)d_in[6];
    const float* bt   = (const float*)d_in[7];
    const float* Wf   = (const float*)d_in[8];
    const float* bf   = (const float*)d_in[9];
    const float* Wf2  = (const float*)d_in[10];
    const float* bf2  = (const float*)d_in[11];
    const float* W1   = (const float*)d_in[12];
    const float* b1   = (const float*)d_in[13];
    const float* W2   = (const float*)d_in[14];
    const float* b2   = (const float*)d_in[15];
    const float* W3   = (const float*)d_in[16];
    const float* b3   = (const float*)d_in[17];
    const float* W4   = (const float*)d_in[18];
    const float* b4   = (const float*)d_in[19];
    float* out = (float*)d_out;

    cudaFuncSetAttribute(disease_kernel,
                         cudaFuncAttributeMaxDynamicSharedMemorySize,
                         (int)sizeof(Smem));
    disease_kernel<<<128, NTHR, sizeof(Smem)>>>(
        xs, A, cell, Wg, bg, attn, Wt, bt, Wf, bf, Wf2, bf2,
        W1, b1, W2, b2, W3, b3, W4, b4, out);
}

// round 4
// speedup vs baseline: 2.1922x; 1.4425x over previous
#include <cuda_runtime.h>

namespace {

constexpr int ATOM   = 34;
constexpr int HID    = 256;
constexpr int LATENT = 128;
constexpr int CELLS  = 512;
constexpr int NN     = 128;
constexpr int XPAD   = 36;             // padded row stride for x/h (16B-aligned rows)
constexpr int HALF   = 64;
constexpr int DIN    = LATENT + CELLS;
constexpr int NTHR   = 512;
constexpr int NWARP  = 16;
constexpr float NEGV = -9e15f;

struct __align__(16) Smem {
    alignas(16) float Wg[3][ATOM][ATOM];
    float bg[3][ATOM];
    float attnv[3][2 * ATOM];
    alignas(16) float Wt[ATOM][HID];
    float bt[HID];
    alignas(16) float Wf[HID][ATOM];
    alignas(16) float Wfc32[HID];
    alignas(16) float Wfc33[HID];
    float bf[ATOM];
    alignas(16) float Wf2[ATOM][LATENT];
    alignas(16) float bf2[LATENT];
    alignas(16) float x[NN][XPAD];
    float xs0[HALF][ATOM];
    alignas(16) float h[NN][XPAD];
    float fsrc[NN];
    float fdst[NN];
    unsigned mask[HALF][4];
    union U {                           // attbuf (GAT) and gbuf (readout) never live together
        float attbuf[NWARP][NN][4];
        float gbuf[NWARP][2][HID];
    } u;
    alignas(16) float dvbuf[NWARP][2][36];
    float wmax[NWARP][LATENT];          // also MLP partial buffer
    float latloc[LATENT];
    float latpeer[LATENT];
    float vec[DIN];
    float h1[128];
    float h2[256];
    float h3own[256];
    float red[NWARP];
    float partial4;                     // written ONLY by rank1 via DSMEM
};

__device__ __forceinline__ float warp_max(float v) {
    #pragma unroll
    for (int off = 16; off; off >>= 1)
        v = fmaxf(v, __shfl_xor_sync(0xffffffffu, v, off));
    return v;
}
__device__ __forceinline__ float warp_sum(float v) {
    #pragma unroll
    for (int off = 16; off; off >>= 1)
        v += __shfl_xor_sync(0xffffffffu, v, off);
    return v;
}
__device__ __forceinline__ unsigned smem_u32(const void* p) {
    return (unsigned)__cvta_generic_to_shared(p);
}
__device__ __forceinline__ unsigned mapa_peer(unsigned local, unsigned rank) {
    unsigned r;
    asm("mapa.shared::cluster.u32 %0, %1, %2;" : "=r"(r) : "r"(local), "r"(rank));
    return r;
}
__device__ __forceinline__ void st_cluster_f32(unsigned addr, float v) {
    asm volatile("st.shared::cluster.f32 [%0], %1;" :: "r"(addr), "f"(v) : "memory");
}
__device__ __forceinline__ void cluster_sync_() {
    asm volatile("barrier.cluster.arrive.aligned;" ::: "memory");
    asm volatile("barrier.cluster.wait.aligned;" ::: "memory");
}
__device__ __forceinline__ unsigned ctarank() {
    unsigned r;
    asm("mov.u32 %0, %%cluster_ctarank;" : "=r"(r));
    return r;
}

__global__ void __launch_bounds__(NTHR, 1) __cluster_dims__(2, 1, 1)
disease_kernel(const float* __restrict__ xs, const int* __restrict__ A,
               const float* __restrict__ cell,
               const float* __restrict__ Wg_g, const float* __restrict__ bg_g,
               const float* __restrict__ attn_g,
               const float* __restrict__ Wt_g, const float* __restrict__ bt_g,
               const float* __restrict__ Wf_g, const float* __restrict__ bf_g,
               const float* __restrict__ Wf2_g, const float* __restrict__ bf2_g,
               const float* __restrict__ W1, const float* __restrict__ b1,
               const float* __restrict__ W2, const float* __restrict__ b2,
               const float* __restrict__ W3, const float* __restrict__ b3,
               const float* __restrict__ W4, const float* __restrict__ b4,
               float* __restrict__ out)
{
    extern __shared__ char smem_raw[];
    Smem& s = *reinterpret_cast<Smem*>(smem_raw);
    const int b     = blockIdx.x >> 1;
    const unsigned rank = ctarank();
    const unsigned prk  = rank ^ 1u;
    const int own0  = (int)rank * HALF;
    const int tid   = threadIdx.x;
    const int lane  = tid & 31;
    const int w     = tid >> 5;

    const unsigned peer_x   = mapa_peer(smem_u32(&s.x[0][0]), prk);
    const unsigned peer_lat = mapa_peer(smem_u32(&s.latpeer[0]), prk);

    // ---------- stage weights + inputs ----------
    for (int i = tid; i < 3 * ATOM * ATOM; i += NTHR) (&s.Wg[0][0][0])[i] = Wg_g[i];
    for (int i = tid; i < 3 * ATOM; i += NTHR)        (&s.bg[0][0])[i]    = bg_g[i];
    for (int i = tid; i < 3 * 2 * ATOM; i += NTHR)    (&s.attnv[0][0])[i] = attn_g[i];
    for (int i = tid; i < ATOM * HID; i += NTHR)      (&s.Wt[0][0])[i]    = Wt_g[i];
    for (int i = tid; i < HID; i += NTHR)             s.bt[i]             = bt_g[i];
    for (int i = tid; i < HID * ATOM; i += NTHR)      (&s.Wf[0][0])[i]    = Wf_g[i];
    for (int i = tid; i < HID; i += NTHR) {
        s.Wfc32[i] = Wf_g[i * ATOM + 32];
        s.Wfc33[i] = Wf_g[i * ATOM + 33];
    }
    for (int i = tid; i < ATOM; i += NTHR)            s.bf[i]             = bf_g[i];
    for (int i = tid; i < ATOM * LATENT; i += NTHR)   (&s.Wf2[0][0])[i]   = Wf2_g[i];
    for (int i = tid; i < LATENT; i += NTHR)          s.bf2[i]            = bf2_g[i];
    for (int i = tid; i < NN * ATOM; i += NTHR) {
        int n = i / ATOM, d = i % ATOM;
        float v = xs[((size_t)b * NN + n) * ATOM + d];
        s.x[n][d] = v;
        if (n >= own0 && n < own0 + HALF) s.xs0[n - own0][d] = v;
    }

    // ---------- adjacency bitmask (own 64 rows) ----------
    {
        const int* __restrict__ Abase = A + (size_t)b * NN * NN;
        #pragma unroll
        for (int t = 0; t < 16; t++) {
            int widx  = w * 16 + t;
            int row   = widx >> 2;
            int chunk = widx & 3;
            int q     = chunk * 32 + lane;
            int av    = Abase[(own0 + row) * NN + q];
            unsigned word = __ballot_sync(0xffffffffu, av > 0);
            if (lane == 0) s.mask[row][chunk] = word;
        }
    }
    __syncthreads();

    // ---------- 3 GAT rounds ----------
    for (int r = 0; r < 3; r++) {
        // h = relu(x @ Wg[r] + bg[r]) : lane = column e (0..31), warp owns 8 rows.
        {
            float wg[ATOM];
            #pragma unroll
            for (int d = 0; d < ATOM; d++) wg[d] = s.Wg[r][d][lane];
            const float bgl = s.bg[r][lane];
            const int n0 = 8 * w;
            #pragma unroll
            for (int j = 0; j < 8; j++) {
                const int n = n0 + j;
                float a0 = bgl, a1 = 0.f;
                #pragma unroll
                for (int db = 0; db < 8; db++) {
                    float4 xv = *reinterpret_cast<const float4*>(&s.x[n][4 * db]);
                    a0 += xv.x * wg[4 * db]     + xv.y * wg[4 * db + 1];
                    a1 += xv.z * wg[4 * db + 2] + xv.w * wg[4 * db + 3];
                }
                float2 x2 = *reinterpret_cast<const float2*>(&s.x[n][32]);
                a0 += x2.x * wg[32];
                a1 += x2.y * wg[33];
                s.h[n][lane] = fmaxf(a0 + a1, 0.f);
            }
        }
        // columns 32,33 mini-pass
        if (tid < 256) {
            const int n = tid >> 1, e = 32 + (tid & 1);
            float a0 = s.bg[r][e], a1 = 0.f;
            #pragma unroll
            for (int d = 0; d < ATOM; d += 2) {
                a0 += s.x[n][d]     * s.Wg[r][d][e];
                a1 += s.x[n][d + 1] * s.Wg[r][d + 1][e];
            }
            s.h[n][e] = fmaxf(a0 + a1, 0.f);
        }
        __syncthreads();

        // fsrc/fdst spread over 256 threads
        if (tid < 256) {
            const int n = tid >> 1, side = tid & 1;
            const float* av = &s.attnv[r][side * ATOM];
            float a0 = 0.f, a1 = 0.f;
            #pragma unroll
            for (int e = 0; e < ATOM; e += 2) {
                a0 += s.h[n][e]     * av[e];
                a1 += s.h[n][e + 1] * av[e + 1];
            }
            (side ? s.fdst : s.fsrc)[n] = a0 + a1;
        }
        // peer must be done reading x before we overwrite below
        cluster_sync_();

        // softmax weights: 4 own rows per warp
        #pragma unroll
        for (int rr = 0; rr < 4; rr++) {
            const int p = own0 + w + 16 * rr;
            const float fs = s.fsrc[p];
            float sc[4];
            #pragma unroll
            for (int j = 0; j < 4; j++) {
                int q = lane + 32 * j;
                float e = fs + s.fdst[q];
                e = e > 0.f ? e : 0.01f * e;
                bool on = (s.mask[p - own0][j] >> lane) & 1u;
                sc[j] = on ? e : NEGV;
            }
            float m = warp_max(fmaxf(fmaxf(sc[0], sc[1]), fmaxf(sc[2], sc[3])));
            float wv[4], sum = 0.f;
            #pragma unroll
            for (int j = 0; j < 4; j++) { wv[j] = __expf(sc[j] - m); sum += wv[j]; }
            sum = warp_sum(sum);
            const float inv = 1.f / sum;
            #pragma unroll
            for (int j = 0; j < 4; j++) s.u.attbuf[w][lane + 32 * j][rr] = wv[j] * inv;
        }
        __syncwarp();

        // msg[d=lane] = sum_q att[q] * h[q][lane]
        float m0[4] = {0.f, 0.f, 0.f, 0.f};
        #pragma unroll 4
        for (int q = 0; q < NN; q++) {
            float hv = s.h[q][lane];
            float4 a = *reinterpret_cast<const float4*>(&s.u.attbuf[w][q][0]);
            m0[0] += a.x * hv;
            m0[1] += a.y * hv;
            m0[2] += a.z * hv;
            m0[3] += a.w * hv;
        }
        float m32[4] = {0.f, 0.f, 0.f, 0.f}, m33[4] = {0.f, 0.f, 0.f, 0.f};
        #pragma unroll
        for (int j = 0; j < 4; j++) {
            int q = lane + 32 * j;
            float h32 = s.h[q][32], h33 = s.h[q][33];
            float4 a = *reinterpret_cast<const float4*>(&s.u.attbuf[w][q][0]);
            m32[0] += a.x * h32; m32[1] += a.y * h32; m32[2] += a.z * h32; m32[3] += a.w * h32;
            m33[0] += a.x * h33; m33[1] += a.y * h33; m33[2] += a.z * h33; m33[3] += a.w * h33;
        }
        #pragma unroll
        for (int rr = 0; rr < 4; rr++) { m32[rr] = warp_sum(m32[rr]); m33[rr] = warp_sum(m33[rr]); }
        #pragma unroll
        for (int rr = 0; rr < 4; rr++) {
            const int p = own0 + w + 16 * rr;
            float nv = s.x[p][lane] + m0[rr];
            s.x[p][lane] = nv;
            st_cluster_f32(peer_x + (unsigned)(p * XPAD + lane) * 4u, nv);
            if (lane == 0) {
                float nv32 = s.x[p][32] + m32[rr];
                float nv33 = s.x[p][33] + m33[rr];
                s.x[p][32] = nv32;
                s.x[p][33] = nv33;
                st_cluster_f32(peer_x + (unsigned)(p * XPAD + 32) * 4u, nv32);
                st_cluster_f32(peer_x + (unsigned)(p * XPAD + 33) * 4u, nv33);
            }
        }
        cluster_sync_();
    }

    // ---------- readout: 4 own rows per warp, batched 2 at a time ----------
    float rmax[4] = {-3.4e38f, -3.4e38f, -3.4e38f, -3.4e38f};
    const int rbase = own0 + 4 * w;
    #pragma unroll
    for (int bt2 = 0; bt2 < 2; bt2++) {
        const int rA = rbase + 2 * bt2;
        const int rB = rA + 1;
        const int e0 = 8 * lane;

        // --- g = relu(x@Wt+bt), 2 rows, lane owns 8 e's ---
        float gA[8], gB[8];
        #pragma unroll
        for (int j = 0; j < 8; j++) { gA[j] = s.bt[e0 + j]; gB[j] = gA[j]; }
        #pragma unroll
        for (int db = 0; db < 8; db++) {
            const int d = 4 * db;
            float4 xA = *reinterpret_cast<const float4*>(&s.x[rA][d]);
            float4 xB = *reinterpret_cast<const float4*>(&s.x[rB][d]);
            #pragma unroll
            for (int dd = 0; dd < 4; dd++) {
                float4 w0 = *reinterpret_cast<const float4*>(&s.Wt[d + dd][e0]);
                float4 w1 = *reinterpret_cast<const float4*>(&s.Wt[d + dd][e0 + 4]);
                float xa = (&xA.x)[dd], xb = (&xB.x)[dd];
                gA[0] += xa * w0.x; gA[1] += xa * w0.y; gA[2] += xa * w0.z; gA[3] += xa * w0.w;
                gA[4] += xa * w1.x; gA[5] += xa * w1.y; gA[6] += xa * w1.z; gA[7] += xa * w1.w;
                gB[0] += xb * w0.x; gB[1] += xb * w0.y; gB[2] += xb * w0.z; gB[3] += xb * w0.w;
                gB[4] += xb * w1.x; gB[5] += xb * w1.y; gB[6] += xb * w1.z; gB[7] += xb * w1.w;
            }
        }
        {
            float2 xA2 = *reinterpret_cast<const float2*>(&s.x[rA][32]);
            float2 xB2 = *reinterpret_cast<const float2*>(&s.x[rB][32]);
            #pragma unroll
            for (int dd = 0; dd < 2; dd++) {
                float4 w0 = *reinterpret_cast<const float4*>(&s.Wt[32 + dd][e0]);
                float4 w1 = *reinterpret_cast<const float4*>(&s.Wt[32 + dd][e0 + 4]);
                float xa = dd ? xA2.y : xA2.x;
                float xb = dd ? xB2.y : xB2.x;
                gA[0] += xa * w0.x; gA[1] += xa * w0.y; gA[2] += xa * w0.z; gA[3] += xa * w0.w;
                gA[4] += xa * w1.x; gA[5] += xa * w1.y; gA[6] += xa * w1.z; gA[7] += xa * w1.w;
                gB[0] += xb * w0.x; gB[1] += xb * w0.y; gB[2] += xb * w0.z; gB[3] += xb * w0.w;
                gB[4] += xb * w1.x; gB[5] += xb * w1.y; gB[6] += xb * w1.z; gB[7] += xb * w1.w;
            }
        }
        #pragma unroll
        for (int j = 0; j < 8; j++) { gA[j] = fmaxf(gA[j], 0.f); gB[j] = fmaxf(gB[j], 0.f); }
        *reinterpret_cast<float4*>(&s.u.gbuf[w][0][e0])     = make_float4(gA[0], gA[1], gA[2], gA[3]);
        *reinterpret_cast<float4*>(&s.u.gbuf[w][0][e0 + 4]) = make_float4(gA[4], gA[5], gA[6], gA[7]);
        *reinterpret_cast<float4*>(&s.u.gbuf[w][1][e0])     = make_float4(gB[0], gB[1], gB[2], gB[3]);
        *reinterpret_cast<float4*>(&s.u.gbuf[w][1][e0 + 4]) = make_float4(gB[4], gB[5], gB[6], gB[7]);
        __syncwarp();

        // --- dv[lane] = sum_e g[e]*Wf[e][lane], 2 rows at once ---
        float a0 = 0.f, a1 = 0.f, a2 = 0.f, a3 = 0.f;
        float c0 = 0.f, c1 = 0.f, c2 = 0.f, c3 = 0.f;
        #pragma unroll 8
        for (int e = 0; e < HID; e += 4) {
            float4 ga = *reinterpret_cast<const float4*>(&s.u.gbuf[w][0][e]);
            float4 gb = *reinterpret_cast<const float4*>(&s.u.gbuf[w][1][e]);
            float wf0 = s.Wf[e][lane];
            float wf1 = s.Wf[e + 1][lane];
            float wf2 = s.Wf[e + 2][lane];
            float wf3 = s.Wf[e + 3][lane];
            a0 += ga.x * wf0; a1 += ga.y * wf1; a2 += ga.z * wf2; a3 += ga.w * wf3;
            c0 += gb.x * wf0; c1 += gb.y * wf1; c2 += gb.z * wf2; c3 += gb.w * wf3;
        }
        float dvA = s.bf[lane] + s.xs0[rA - own0][lane] + (a0 + a1) + (a2 + a3);
        float dvB = s.bf[lane] + s.xs0[rB - own0][lane] + (c0 + c1) + (c2 + c3);

        // --- d[32], d[33] from register g ---
        float pA32, pA33, pB32, pB33;
        {
            float4 c32a = *reinterpret_cast<const float4*>(&s.Wfc32[e0]);
            float4 c32b = *reinterpret_cast<const float4*>(&s.Wfc32[e0 + 4]);
            float4 c33a = *reinterpret_cast<const float4*>(&s.Wfc33[e0]);
            float4 c33b = *reinterpret_cast<const float4*>(&s.Wfc33[e0 + 4]);
            pA32 = gA[0]*c32a.x + gA[1]*c32a.y + gA[2]*c32a.z + gA[3]*c32a.w
                 + gA[4]*c32b.x + gA[5]*c32b.y + gA[6]*c32b.z + gA[7]*c32b.w;
            pA33 = gA[0]*c33a.x + gA[1]*c33a.y + gA[2]*c33a.z + gA[3]*c33a.w
                 + gA[4]*c33b.x + gA[5]*c33b.y + gA[6]*c33b.z + gA[7]*c33b.w;
            pB32 = gB[0]*c32a.x + gB[1]*c32a.y + gB[2]*c32a.z + gB[3]*c32a.w
                 + gB[4]*c32b.x + gB[5]*c32b.y + gB[6]*c32b.z + gB[7]*c32b.w;
            pB33 = gB[0]*c33a.x + gB[1]*c33a.y + gB[2]*c33a.z + gB[3]*c33a.w
                 + gB[4]*c33b.x + gB[5]*c33b.y + gB[6]*c33b.z + gB[7]*c33b.w;
        }
        pA32 = warp_sum(pA32); pA33 = warp_sum(pA33);
        pB32 = warp_sum(pB32); pB33 = warp_sum(pB33);
        s.dvbuf[w][0][lane] = dvA;
        s.dvbuf[w][1][lane] = dvB;
        if (lane == 0) {
            s.dvbuf[w][0][32] = pA32 + s.bf[32] + s.xs0[rA - own0][32];
            s.dvbuf[w][0][33] = pA33 + s.bf[33] + s.xs0[rA - own0][33];
            s.dvbuf[w][1][32] = pB32 + s.bf[32] + s.xs0[rB - own0][32];
            s.dvbuf[w][1][33] = pB33 + s.bf[33] + s.xs0[rB - own0][33];
        }
        __syncwarp();

        // --- latent = dv @ Wf2 + bf2, lane owns 4 latents, 2 rows ---
        {
            const int l0 = 4 * lane;
            float4 accA = *reinterpret_cast<const float4*>(&s.bf2[l0]);
            float4 accB = accA;
            #pragma unroll
            for (int db = 0; db < 8; db++) {
                const int d = 4 * db;
                float4 dA = *reinterpret_cast<const float4*>(&s.dvbuf[w][0][d]);
                float4 dB = *reinterpret_cast<const float4*>(&s.dvbuf[w][1][d]);
                #pragma unroll
                for (int dd = 0; dd < 4; dd++) {
                    float4 wv = *reinterpret_cast<const float4*>(&s.Wf2[d + dd][l0]);
                    float da = (&dA.x)[dd], db2 = (&dB.x)[dd];
                    accA.x += da * wv.x;  accA.y += da * wv.y;
                    accA.z += da * wv.z;  accA.w += da * wv.w;
                    accB.x += db2 * wv.x; accB.y += db2 * wv.y;
                    accB.z += db2 * wv.z; accB.w += db2 * wv.w;
                }
            }
            {
                float2 dA2 = *reinterpret_cast<const float2*>(&s.dvbuf[w][0][32]);
                float2 dB2 = *reinterpret_cast<const float2*>(&s.dvbuf[w][1][32]);
                float4 w32 = *reinterpret_cast<const float4*>(&s.Wf2[32][l0]);
                float4 w33 = *reinterpret_cast<const float4*>(&s.Wf2[33][l0]);
                accA.x += dA2.x * w32.x + dA2.y * w33.x;
                accA.y += dA2.x * w32.y + dA2.y * w33.y;
                accA.z += dA2.x * w32.z + dA2.y * w33.z;
                accA.w += dA2.x * w32.w + dA2.y * w33.w;
                accB.x += dB2.x * w32.x + dB2.y * w33.x;
                accB.y += dB2.x * w32.y + dB2.y * w33.y;
                accB.z += dB2.x * w32.z + dB2.y * w33.z;
                accB.w += dB2.x * w32.w + dB2.y * w33.w;
            }
            rmax[0] = fmaxf(rmax[0], fmaxf(accA.x, accB.x));
            rmax[1] = fmaxf(rmax[1], fmaxf(accA.y, accB.y));
            rmax[2] = fmaxf(rmax[2], fmaxf(accA.z, accB.z));
            rmax[3] = fmaxf(rmax[3], fmaxf(accA.w, accB.w));
        }
        __syncwarp();
    }
    #pragma unroll
    for (int j = 0; j < 4; j++) s.wmax[w][4 * lane + j] = rmax[j];
    __syncthreads();

    // ---------- row-max combine + cluster exchange ----------
    if (tid < LATENT) {
        float m = s.wmax[0][tid];
        #pragma unroll
        for (int ww = 1; ww < NWARP; ww++) m = fmaxf(m, s.wmax[ww][tid]);
        s.latloc[tid] = m;
        st_cluster_f32(peer_lat + (unsigned)tid * 4u, m);
    }
    cluster_sync_();

    if (tid < LATENT) {
        float m = fmaxf(s.latloc[tid], s.latpeer[tid]);
        s.vec[tid] = 1.f / (1.f + __expf(-m));
    }
    for (int j = tid; j < CELLS; j += NTHR) {
        float c = cell[(size_t)b * CELLS + j];
        s.vec[LATENT + j] = 1.f / (1.f + __expf(-c));
    }
    __syncthreads();

    const unsigned peer_h1 = mapa_peer(smem_u32(&s.h1[0]), prk);
    const unsigned peer_h2 = mapa_peer(smem_u32(&s.h2[0]), prk);
    const unsigned peer_p4 = mapa_peer(smem_u32(&s.partial4), prk);

    // ---------- MLP L1: 640 -> 128, own 64 columns ----------
    {
        const int o = tid & 63, part = tid >> 6;
        const int og = own0 + o;
        const int k0 = part * 80;
        float a0 = 0.f, a1 = 0.f, a2 = 0.f, a3 = 0.f;
        #pragma unroll 4
        for (int k = k0; k < k0 + 80; k += 4) {
            a0 += s.vec[k]     * W1[(k)     * 128 + og];
            a1 += s.vec[k + 1] * W1[(k + 1) * 128 + og];
            a2 += s.vec[k + 2] * W1[(k + 2) * 128 + og];
            a3 += s.vec[k + 3] * W1[(k + 3) * 128 + og];
        }
        (&s.wmax[0][0])[part * 64 + o] = (a0 + a1) + (a2 + a3);
    }
    __syncthreads();
    if (tid < 64) {
        const int og = own0 + tid;
        float v = b1[og];
        #pragma unroll
        for (int p = 0; p < 8; p++) v += (&s.wmax[0][0])[p * 64 + tid];
        v = fmaxf(v, 0.f);
        s.h1[og] = v;
        st_cluster_f32(peer_h1 + (unsigned)og * 4u, v);
    }
    cluster_sync_();

    // ---------- MLP L2: 128 -> 256, own 128 columns ----------
    {
        const int o = tid & 127, part = tid >> 7;
        const int og = (int)rank * 128 + o;
        const int k0 = part * 32;
        float a0 = 0.f, a1 = 0.f, a2 = 0.f, a3 = 0.f;
        #pragma unroll 4
        for (int k = k0; k < k0 + 32; k += 4) {
            a0 += s.h1[k]     * W2[(k)     * 256 + og];
            a1 += s.h1[k + 1] * W2[(k + 1) * 256 + og];
            a2 += s.h1[k + 2] * W2[(k + 2) * 256 + og];
            a3 += s.h1[k + 3] * W2[(k + 3) * 256 + og];
        }
        (&s.wmax[0][0])[part * 128 + o] = (a0 + a1) + (a2 + a3);
    }
    __syncthreads();
    if (tid < 128) {
        const int og = (int)rank * 128 + tid;
        float v = b2[og];
        #pragma unroll
        for (int p = 0; p < 4; p++) v += (&s.wmax[0][0])[p * 128 + tid];
        v = fmaxf(v, 0.f);
        s.h2[og] = v;
        st_cluster_f32(peer_h2 + (unsigned)og * 4u, v);
    }
    cluster_sync_();

    // ---------- MLP L3: 256 -> 512, own 256 columns ----------
    {
        const int o = tid & 255, part = tid >> 8;
        const int og = (int)rank * 256 + o;
        const int k0 = part * 128;
        float a0 = 0.f, a1 = 0.f, a2 = 0.f, a3 = 0.f;
        #pragma unroll 4
        for (int k = k0; k < k0 + 128; k += 4) {
            a0 += s.h2[k]     * W3[(k)     * 512 + og];
            a1 += s.h2[k + 1] * W3[(k + 1) * 512 + og];
            a2 += s.h2[k + 2] * W3[(k + 2) * 512 + og];
            a3 += s.h2[k + 3] * W3[(k + 3) * 512 + og];
        }
        (&s.wmax[0][0])[part * 256 + o] = (a0 + a1) + (a2 + a3);
    }
    __syncthreads();
    if (tid < 256) {
        float v = b3[(int)rank * 256 + tid]
                + (&s.wmax[0][0])[tid] + (&s.wmax[0][0])[256 + tid];
        s.h3own[tid] = fmaxf(v, 0.f);
    }
    __syncthreads();

    // ---------- MLP L4: 512 -> 1 ----------
    {
        float acc = 0.f;
        if (tid < 256) acc = s.h3own[tid] * W4[(int)rank * 256 + tid];
        acc = warp_sum(acc);
        if (lane == 0) s.red[w] = acc;
    }
    __syncthreads();
    if (rank == 1 && tid == 0) {
        float acc = 0.f;
        #pragma unroll
        for (int ww = 0; ww < 8; ww++) acc += s.red[ww];
        st_cluster_f32(peer_p4, acc);
    }
    cluster_sync_();
    if (rank == 0 && tid == 0) {
        float acc = 0.f;
        #pragma unroll
        for (int ww = 0; ww < 8; ww++) acc += s.red[ww];
        out[b] = acc + s.partial4 + b4[0];
    }
}

} // namespace

extern "C" void kernel_launch(void* const* d_in, const int* in_sizes, int n_in,
                              void* d_out, int out_size) {
    (void)in_sizes; (void)n_in; (void)out_size;
    const float* xs   = (const float*)d_in[0];
    const int*   A    = (const int*)d_in[1];
    const float* cell = (const float*)d_in[2];
    const float* Wg   = (const float*)d_in[3];
    const float* bg   = (const float*)d_in[4];
    const float* attn = (const float*)d_in[5];
    const float* Wt   = (const float*)d_in[6];
    const float* bt   = (const float*)d_in[7];
    const float* Wf   = (const float*)d_in[8];
    const float* bf   = (const float*)d_in[9];
    const float* Wf2  = (const float*)d_in[10];
    const float* bf2  = (const float*)d_in[11];
    const float* W1   = (const float*)d_in[12];
    const float* b1   = (const float*)d_in[13];
    const float* W2   = (const float*)d_in[14];
    const float* b2   = (const float*)d_in[15];
    const float* W3   = (const float*)d_in[16];
    const float* b3   = (const float*)d_in[17];
    const float* W4   = (const float*)d_in[18];
    const float* b4   = (const float*)d_in[19];
    float* out = (float*)d_out;

    cudaFuncSetAttribute(disease_kernel,
                         cudaFuncAttributeMaxDynamicSharedMemorySize,
                         (int)sizeof(Smem));
    disease_kernel<<<128, NTHR, sizeof(Smem)>>>(
        xs, A, cell, Wg, bg, attn, Wt, bt, Wf, bf, Wf2, bf2,
        W1, b1, W2, b2, W3, b3, W4, b4, out);
}

// round 5
// speedup vs baseline: 2.3227x; 1.0595x over previous
#include <cuda_runtime.h>

namespace {

typedef unsigned long long u64;

constexpr int ATOM   = 34;
constexpr int HID    = 256;
constexpr int LATENT = 128;
constexpr int CELLS  = 512;
constexpr int NN     = 128;
constexpr int XPAD   = 36;
constexpr int HALF   = 64;
constexpr int DIN    = LATENT + CELLS;
constexpr int NTHR   = 512;
constexpr int NWARP  = 16;
constexpr float NEGV = -9e15f;

#define FMA2(d, a, b, c) asm("fma.rn.f32x2 %0, %1, %2, %3;" : "=l"(d) : "l"(a), "l"(b), "l"(c))

__device__ __forceinline__ u64 pack2(float lo, float hi) {
    u64 r; asm("mov.b64 %0, {%1, %2};" : "=l"(r) : "f"(lo), "f"(hi)); return r;
}
__device__ __forceinline__ float2 unpack2(u64 v) {
    float lo, hi; asm("mov.b64 {%0, %1}, %2;" : "=f"(lo), "=f"(hi) : "l"(v));
    return make_float2(lo, hi);
}
union F4U2 { float4 f4; struct { u64 lo, hi; } u; };

struct __align__(16) Smem {
    alignas(16) float Wg[3][ATOM][ATOM];
    float bg[3][ATOM];
    float attnv[3][2 * ATOM];
    alignas(16) float Wt[ATOM][HID];
    alignas(16) float bt[HID];
    alignas(16) float2 WfP[HID / 2][32];   // (Wf[2p][l], Wf[2p+1][l])
    alignas(16) float Wfc32[HID];
    alignas(16) float Wfc33[HID];
    float bf[ATOM];
    alignas(16) float Wf2[ATOM][LATENT];
    alignas(16) float bf2[LATENT];
    alignas(16) float x0[NN][XPAD];
    alignas(16) float x1[NN][XPAD];
    float xs0[HALF][ATOM];
    alignas(16) float h[NN][XPAD];
    float fsrc[NN];
    float fdst[NN];
    unsigned mask[HALF][4];
    union U {
        float attbuf[NWARP][NN][4];
        float gbuf[NWARP][2][HID];
    } u;
    alignas(16) float dvbuf[NWARP][2][36];
    alignas(16) float wmax[NWARP][LATENT];  // also MLP partial buffer
    float latloc[LATENT];
    float latpeer[LATENT];
    float vec[DIN];
    alignas(16) float h1[128];
    alignas(16) float h2[256];
    alignas(16) float h3own[256];
    float red[NWARP];
    float partial4;                         // written ONLY by rank1 via DSMEM
};

__device__ __forceinline__ float warp_max(float v) {
    #pragma unroll
    for (int off = 16; off; off >>= 1)
        v = fmaxf(v, __shfl_xor_sync(0xffffffffu, v, off));
    return v;
}
__device__ __forceinline__ float warp_sum(float v) {
    #pragma unroll
    for (int off = 16; off; off >>= 1)
        v += __shfl_xor_sync(0xffffffffu, v, off);
    return v;
}
__device__ __forceinline__ unsigned smem_u32(const void* p) {
    return (unsigned)__cvta_generic_to_shared(p);
}
__device__ __forceinline__ unsigned mapa_peer(unsigned local, unsigned rank) {
    unsigned r;
    asm("mapa.shared::cluster.u32 %0, %1, %2;" : "=r"(r) : "r"(local), "r"(rank));
    return r;
}
__device__ __forceinline__ void st_cluster_f32(unsigned addr, float v) {
    asm volatile("st.shared::cluster.f32 [%0], %1;" :: "r"(addr), "f"(v) : "memory");
}
__device__ __forceinline__ void st_cluster_u64(unsigned addr, u64 v) {
    asm volatile("st.shared::cluster.b64 [%0], %1;" :: "r"(addr), "l"(v) : "memory");
}
__device__ __forceinline__ void cluster_sync_() {
    asm volatile("barrier.cluster.arrive.aligned;" ::: "memory");
    asm volatile("barrier.cluster.wait.aligned;" ::: "memory");
}
__device__ __forceinline__ unsigned ctarank() {
    unsigned r;
    asm("mov.u32 %0, %%cluster_ctarank;" : "=r"(r));
    return r;
}

__global__ void __launch_bounds__(NTHR, 1) __cluster_dims__(2, 1, 1)
disease_kernel(const float* __restrict__ xs, const int* __restrict__ A,
               const float* __restrict__ cell,
               const float* __restrict__ Wg_g, const float* __restrict__ bg_g,
               const float* __restrict__ attn_g,
               const float* __restrict__ Wt_g, const float* __restrict__ bt_g,
               const float* __restrict__ Wf_g, const float* __restrict__ bf_g,
               const float* __restrict__ Wf2_g, const float* __restrict__ bf2_g,
               const float* __restrict__ W1, const float* __restrict__ b1,
               const float* __restrict__ W2, const float* __restrict__ b2,
               const float* __restrict__ W3, const float* __restrict__ b3,
               const float* __restrict__ W4, const float* __restrict__ b4,
               float* __restrict__ out)
{
    extern __shared__ char smem_raw[];
    Smem& s = *reinterpret_cast<Smem*>(smem_raw);
    const int b     = blockIdx.x >> 1;
    const unsigned rank = ctarank();
    const unsigned prk  = rank ^ 1u;
    const int own0  = (int)rank * HALF;
    const int tid   = threadIdx.x;
    const int lane  = tid & 31;
    const int w     = tid >> 5;

    const unsigned peer_x0  = mapa_peer(smem_u32(&s.x0[0][0]), prk);
    const unsigned peer_x1  = mapa_peer(smem_u32(&s.x1[0][0]), prk);
    const unsigned peer_lat = mapa_peer(smem_u32(&s.latpeer[0]), prk);

    // ---------- stage weights + inputs ----------
    for (int i = tid; i < 3 * ATOM * ATOM; i += NTHR) (&s.Wg[0][0][0])[i] = Wg_g[i];
    for (int i = tid; i < 3 * ATOM; i += NTHR)        (&s.bg[0][0])[i]    = bg_g[i];
    for (int i = tid; i < 3 * 2 * ATOM; i += NTHR)    (&s.attnv[0][0])[i] = attn_g[i];
    for (int i = tid; i < ATOM * HID; i += NTHR)      (&s.Wt[0][0])[i]    = Wt_g[i];
    for (int i = tid; i < HID; i += NTHR)             s.bt[i]             = bt_g[i];
    for (int i = tid; i < (HID / 2) * 32; i += NTHR) {
        int p = i >> 5, l = i & 31;
        s.WfP[p][l] = make_float2(Wf_g[(2 * p) * ATOM + l], Wf_g[(2 * p + 1) * ATOM + l]);
    }
    for (int i = tid; i < HID; i += NTHR) {
        s.Wfc32[i] = Wf_g[i * ATOM + 32];
        s.Wfc33[i] = Wf_g[i * ATOM + 33];
    }
    for (int i = tid; i < ATOM; i += NTHR)            s.bf[i]             = bf_g[i];
    for (int i = tid; i < ATOM * LATENT; i += NTHR)   (&s.Wf2[0][0])[i]   = Wf2_g[i];
    for (int i = tid; i < LATENT; i += NTHR)          s.bf2[i]            = bf2_g[i];
    for (int i = tid; i < NN * ATOM; i += NTHR) {
        int n = i / ATOM, d = i % ATOM;
        float v = xs[((size_t)b * NN + n) * ATOM + d];
        s.x0[n][d] = v;
        if (n >= own0 && n < own0 + HALF) s.xs0[n - own0][d] = v;
    }

    // ---------- adjacency bitmask (own 64 rows) ----------
    {
        const int* __restrict__ Abase = A + (size_t)b * NN * NN;
        #pragma unroll
        for (int t = 0; t < 16; t++) {
            int widx  = w * 16 + t;
            int row   = widx >> 2;
            int chunk = widx & 3;
            int q     = chunk * 32 + lane;
            int av    = Abase[(own0 + row) * NN + q];
            unsigned word = __ballot_sync(0xffffffffu, av > 0);
            if (lane == 0) s.mask[row][chunk] = word;
        }
    }
    __syncthreads();

    // ---------- 3 GAT rounds, double-buffered x ----------
    float (*xc)[XPAD] = s.x0;
    float (*xn)[XPAD] = s.x1;
    unsigned peer_xn = peer_x1;

    for (int r = 0; r < 3; r++) {
        // h = relu(x @ Wg + bg): lane = col e<32, warp owns 8 rows, f32x2 math.
        {
            u64 wgp[17];
            #pragma unroll
            for (int k = 0; k < 17; k++)
                wgp[k] = pack2(s.Wg[r][2 * k][lane], s.Wg[r][2 * k + 1][lane]);
            const float bgl = s.bg[r][lane];
            const int n0 = 8 * w;
            #pragma unroll
            for (int j = 0; j < 8; j++) {
                const int n = n0 + j;
                u64 acc0 = pack2(bgl, 0.f);
                u64 acc1 = 0ull;
                #pragma unroll
                for (int db = 0; db < 8; db++) {
                    F4U2 xv; xv.f4 = *reinterpret_cast<const float4*>(&xc[n][4 * db]);
                    FMA2(acc0, xv.u.lo, wgp[2 * db],     acc0);
                    FMA2(acc1, xv.u.hi, wgp[2 * db + 1], acc1);
                }
                u64 x2 = *reinterpret_cast<const u64*>(&xc[n][32]);
                FMA2(acc0, x2, wgp[16], acc0);
                float2 a = unpack2(acc0), c = unpack2(acc1);
                s.h[n][lane] = fmaxf((a.x + a.y) + (c.x + c.y), 0.f);
            }
        }
        // columns 32,33 mini-pass
        if (tid < 256) {
            const int n = tid >> 1, e = 32 + (tid & 1);
            float a0 = s.bg[r][e], a1 = 0.f;
            #pragma unroll
            for (int d = 0; d < ATOM; d += 2) {
                a0 += xc[n][d]     * s.Wg[r][d][e];
                a1 += xc[n][d + 1] * s.Wg[r][d + 1][e];
            }
            s.h[n][e] = fmaxf(a0 + a1, 0.f);
        }
        __syncthreads();

        // fsrc/fdst
        if (tid < 256) {
            const int n = tid >> 1, side = tid & 1;
            const float* av = &s.attnv[r][side * ATOM];
            float a0 = 0.f, a1 = 0.f;
            #pragma unroll
            for (int e = 0; e < ATOM; e += 2) {
                a0 += s.h[n][e]     * av[e];
                a1 += s.h[n][e + 1] * av[e + 1];
            }
            (side ? s.fdst : s.fsrc)[n] = a0 + a1;
        }
        __syncthreads();

        // softmax weights: 4 own rows per warp
        #pragma unroll
        for (int rr = 0; rr < 4; rr++) {
            const int p = own0 + w + 16 * rr;
            const float fs = s.fsrc[p];
            float sc[4];
            #pragma unroll
            for (int j = 0; j < 4; j++) {
                int q = lane + 32 * j;
                float e = fs + s.fdst[q];
                e = e > 0.f ? e : 0.01f * e;
                bool on = (s.mask[p - own0][j] >> lane) & 1u;
                sc[j] = on ? e : NEGV;
            }
            float m = warp_max(fmaxf(fmaxf(sc[0], sc[1]), fmaxf(sc[2], sc[3])));
            float wv[4], sum = 0.f;
            #pragma unroll
            for (int j = 0; j < 4; j++) { wv[j] = __expf(sc[j] - m); sum += wv[j]; }
            sum = warp_sum(sum);
            const float inv = 1.f / sum;
            #pragma unroll
            for (int j = 0; j < 4; j++) s.u.attbuf[w][lane + 32 * j][rr] = wv[j] * inv;
        }
        __syncwarp();

        // msg[d=lane] for 4 rows, f32x2
        u64 macc0 = 0ull, macc1 = 0ull;
        #pragma unroll 4
        for (int q = 0; q < NN; q++) {
            float hv = s.h[q][lane];
            F4U2 a; a.f4 = *reinterpret_cast<const float4*>(&s.u.attbuf[w][q][0]);
            u64 hp = pack2(hv, hv);
            FMA2(macc0, a.u.lo, hp, macc0);
            FMA2(macc1, a.u.hi, hp, macc1);
        }
        float2 mlo = unpack2(macc0), mhi = unpack2(macc1);
        float m0[4] = {mlo.x, mlo.y, mhi.x, mhi.y};

        float m32[4] = {0.f, 0.f, 0.f, 0.f}, m33[4] = {0.f, 0.f, 0.f, 0.f};
        #pragma unroll
        for (int j = 0; j < 4; j++) {
            int q = lane + 32 * j;
            float h32 = s.h[q][32], h33 = s.h[q][33];
            float4 a = *reinterpret_cast<const float4*>(&s.u.attbuf[w][q][0]);
            m32[0] += a.x * h32; m32[1] += a.y * h32; m32[2] += a.z * h32; m32[3] += a.w * h32;
            m33[0] += a.x * h33; m33[1] += a.y * h33; m33[2] += a.z * h33; m33[3] += a.w * h33;
        }
        #pragma unroll
        for (int rr = 0; rr < 4; rr++) { m32[rr] = warp_sum(m32[rr]); m33[rr] = warp_sum(m33[rr]); }
        #pragma unroll
        for (int rr = 0; rr < 4; rr++) {
            const int p = own0 + w + 16 * rr;
            float nv = xc[p][lane] + m0[rr];
            xn[p][lane] = nv;
            st_cluster_f32(peer_xn + (unsigned)(p * XPAD + lane) * 4u, nv);
            if (lane == 0) {
                float nv32 = xc[p][32] + m32[rr];
                float nv33 = xc[p][33] + m33[rr];
                xn[p][32] = nv32;
                xn[p][33] = nv33;
                st_cluster_f32(peer_xn + (unsigned)(p * XPAD + 32) * 4u, nv32);
                st_cluster_f32(peer_xn + (unsigned)(p * XPAD + 33) * 4u, nv33);
            }
        }
        cluster_sync_();
        { float (*t)[XPAD] = xc; xc = xn; xn = t; }
        peer_xn = (peer_xn == peer_x1) ? peer_x0 : peer_x1;
    }

    // ---------- readout: 4 own rows per warp, 2 at a time, f32x2 ----------
    float rmax[4] = {-3.4e38f, -3.4e38f, -3.4e38f, -3.4e38f};
    const int rbase = own0 + 4 * w;
    #pragma unroll
    for (int bt2 = 0; bt2 < 2; bt2++) {
        const int rA = rbase + 2 * bt2;
        const int rB = rA + 1;
        const int e0 = 8 * lane;

        // g = relu(x@Wt+bt), 2 rows, lane owns 8 e's as 4 pairs
        u64 gAp[4], gBp[4];
        #pragma unroll
        for (int k = 0; k < 4; k++) {
            u64 btp = *reinterpret_cast<const u64*>(&s.bt[e0 + 2 * k]);
            gAp[k] = btp; gBp[k] = btp;
        }
        #pragma unroll
        for (int db = 0; db < 8; db++) {
            const int d = 4 * db;
            float4 xA = *reinterpret_cast<const float4*>(&xc[rA][d]);
            float4 xB = *reinterpret_cast<const float4*>(&xc[rB][d]);
            #pragma unroll
            for (int dd = 0; dd < 4; dd++) {
                F4U2 w0; w0.f4 = *reinterpret_cast<const float4*>(&s.Wt[d + dd][e0]);
                F4U2 w1; w1.f4 = *reinterpret_cast<const float4*>(&s.Wt[d + dd][e0 + 4]);
                u64 xap = pack2((&xA.x)[dd], (&xA.x)[dd]);
                u64 xbp = pack2((&xB.x)[dd], (&xB.x)[dd]);
                FMA2(gAp[0], w0.u.lo, xap, gAp[0]);
                FMA2(gAp[1], w0.u.hi, xap, gAp[1]);
                FMA2(gAp[2], w1.u.lo, xap, gAp[2]);
                FMA2(gAp[3], w1.u.hi, xap, gAp[3]);
                FMA2(gBp[0], w0.u.lo, xbp, gBp[0]);
                FMA2(gBp[1], w0.u.hi, xbp, gBp[1]);
                FMA2(gBp[2], w1.u.lo, xbp, gBp[2]);
                FMA2(gBp[3], w1.u.hi, xbp, gBp[3]);
            }
        }
        {
            float2 xA2 = *reinterpret_cast<const float2*>(&xc[rA][32]);
            float2 xB2 = *reinterpret_cast<const float2*>(&xc[rB][32]);
            #pragma unroll
            for (int dd = 0; dd < 2; dd++) {
                F4U2 w0; w0.f4 = *reinterpret_cast<const float4*>(&s.Wt[32 + dd][e0]);
                F4U2 w1; w1.f4 = *reinterpret_cast<const float4*>(&s.Wt[32 + dd][e0 + 4]);
                float xa = dd ? xA2.y : xA2.x;
                float xb = dd ? xB2.y : xB2.x;
                u64 xap = pack2(xa, xa), xbp = pack2(xb, xb);
                FMA2(gAp[0], w0.u.lo, xap, gAp[0]);
                FMA2(gAp[1], w0.u.hi, xap, gAp[1]);
                FMA2(gAp[2], w1.u.lo, xap, gAp[2]);
                FMA2(gAp[3], w1.u.hi, xap, gAp[3]);
                FMA2(gBp[0], w0.u.lo, xbp, gBp[0]);
                FMA2(gBp[1], w0.u.hi, xbp, gBp[1]);
                FMA2(gBp[2], w1.u.lo, xbp, gBp[2]);
                FMA2(gBp[3], w1.u.hi, xbp, gBp[3]);
            }
        }
        // relu + store pairs to gbuf
        #pragma unroll
        for (int k = 0; k < 4; k++) {
            float2 ga = unpack2(gAp[k]);
            float2 gb = unpack2(gBp[k]);
            ga.x = fmaxf(ga.x, 0.f); ga.y = fmaxf(ga.y, 0.f);
            gb.x = fmaxf(gb.x, 0.f); gb.y = fmaxf(gb.y, 0.f);
            gAp[k] = pack2(ga.x, ga.y);
            gBp[k] = pack2(gb.x, gb.y);
            *reinterpret_cast<u64*>(&s.u.gbuf[w][0][e0 + 2 * k]) = gAp[k];
            *reinterpret_cast<u64*>(&s.u.gbuf[w][1][e0 + 2 * k]) = gBp[k];
        }
        __syncwarp();

        // dv[lane] = sum_e g[e]*Wf[e][lane], 2 rows, pair-packed Wf
        u64 dA0 = 0ull, dA1 = 0ull, dB0 = 0ull, dB1 = 0ull;
        #pragma unroll 8
        for (int e = 0; e < HID; e += 4) {
            u64 wf0 = *reinterpret_cast<const u64*>(&s.WfP[(e >> 1)][lane]);
            u64 wf1 = *reinterpret_cast<const u64*>(&s.WfP[(e >> 1) + 1][lane]);
            F4U2 ga; ga.f4 = *reinterpret_cast<const float4*>(&s.u.gbuf[w][0][e]);
            F4U2 gb; gb.f4 = *reinterpret_cast<const float4*>(&s.u.gbuf[w][1][e]);
            FMA2(dA0, ga.u.lo, wf0, dA0);
            FMA2(dA1, ga.u.hi, wf1, dA1);
            FMA2(dB0, gb.u.lo, wf0, dB0);
            FMA2(dB1, gb.u.hi, wf1, dB1);
        }
        float2 a0 = unpack2(dA0), a1 = unpack2(dA1);
        float2 c0 = unpack2(dB0), c1 = unpack2(dB1);
        float dvA = s.bf[lane] + s.xs0[rA - own0][lane] + ((a0.x + a0.y) + (a1.x + a1.y));
        float dvB = s.bf[lane] + s.xs0[rB - own0][lane] + ((c0.x + c0.y) + (c1.x + c1.y));

        // d[32], d[33] partials from register g (f32x2)
        u64 aA32 = 0ull, aA33 = 0ull, aB32 = 0ull, aB33 = 0ull;
        {
            F4U2 c32a; c32a.f4 = *reinterpret_cast<const float4*>(&s.Wfc32[e0]);
            F4U2 c32b; c32b.f4 = *reinterpret_cast<const float4*>(&s.Wfc32[e0 + 4]);
            F4U2 c33a; c33a.f4 = *reinterpret_cast<const float4*>(&s.Wfc33[e0]);
            F4U2 c33b; c33b.f4 = *reinterpret_cast<const float4*>(&s.Wfc33[e0 + 4]);
            u64 c32p[4] = {c32a.u.lo, c32a.u.hi, c32b.u.lo, c32b.u.hi};
            u64 c33p[4] = {c33a.u.lo, c33a.u.hi, c33b.u.lo, c33b.u.hi};
            #pragma unroll
            for (int k = 0; k < 4; k++) {
                FMA2(aA32, gAp[k], c32p[k], aA32);
                FMA2(aA33, gAp[k], c33p[k], aA33);
                FMA2(aB32, gBp[k], c32p[k], aB32);
                FMA2(aB33, gBp[k], c33p[k], aB33);
            }
        }
        float2 tA32 = unpack2(aA32), tA33 = unpack2(aA33);
        float2 tB32 = unpack2(aB32), tB33 = unpack2(aB33);
        float pA32 = warp_sum(tA32.x + tA32.y);
        float pA33 = warp_sum(tA33.x + tA33.y);
        float pB32 = warp_sum(tB32.x + tB32.y);
        float pB33 = warp_sum(tB33.x + tB33.y);
        s.dvbuf[w][0][lane] = dvA;
        s.dvbuf[w][1][lane] = dvB;
        if (lane == 0) {
            s.dvbuf[w][0][32] = pA32 + s.bf[32] + s.xs0[rA - own0][32];
            s.dvbuf[w][0][33] = pA33 + s.bf[33] + s.xs0[rA - own0][33];
            s.dvbuf[w][1][32] = pB32 + s.bf[32] + s.xs0[rB - own0][32];
            s.dvbuf[w][1][33] = pB33 + s.bf[33] + s.xs0[rB - own0][33];
        }
        __syncwarp();

        // latent = dv @ Wf2 + bf2, lane owns 4 latents (2 pairs), 2 rows
        {
            const int l0 = 4 * lane;
            u64 accA0 = *reinterpret_cast<const u64*>(&s.bf2[l0]);
            u64 accA1 = *reinterpret_cast<const u64*>(&s.bf2[l0 + 2]);
            u64 accB0 = accA0, accB1 = accA1;
            #pragma unroll
            for (int db = 0; db < 8; db++) {
                const int d = 4 * db;
                float4 dA4 = *reinterpret_cast<const float4*>(&s.dvbuf[w][0][d]);
                float4 dB4 = *reinterpret_cast<const float4*>(&s.dvbuf[w][1][d]);
                #pragma unroll
                for (int dd = 0; dd < 4; dd++) {
                    F4U2 wv; wv.f4 = *reinterpret_cast<const float4*>(&s.Wf2[d + dd][l0]);
                    u64 dap = pack2((&dA4.x)[dd], (&dA4.x)[dd]);
                    u64 dbp = pack2((&dB4.x)[dd], (&dB4.x)[dd]);
                    FMA2(accA0, wv.u.lo, dap, accA0);
                    FMA2(accA1, wv.u.hi, dap, accA1);
                    FMA2(accB0, wv.u.lo, dbp, accB0);
                    FMA2(accB1, wv.u.hi, dbp, accB1);
                }
            }
            {
                float2 dA2 = *reinterpret_cast<const float2*>(&s.dvbuf[w][0][32]);
                float2 dB2 = *reinterpret_cast<const float2*>(&s.dvbuf[w][1][32]);
                F4U2 w32; w32.f4 = *reinterpret_cast<const float4*>(&s.Wf2[32][l0]);
                F4U2 w33; w33.f4 = *reinterpret_cast<const float4*>(&s.Wf2[33][l0]);
                u64 a32p = pack2(dA2.x, dA2.x), a33p = pack2(dA2.y, dA2.y);
                u64 b32p = pack2(dB2.x, dB2.x), b33p = pack2(dB2.y, dB2.y);
                FMA2(accA0, w32.u.lo, a32p, accA0);
                FMA2(accA1, w32.u.hi, a32p, accA1);
                FMA2(accA0, w33.u.lo, a33p, accA0);
                FMA2(accA1, w33.u.hi, a33p, accA1);
                FMA2(accB0, w32.u.lo, b32p, accB0);
                FMA2(accB1, w32.u.hi, b32p, accB1);
                FMA2(accB0, w33.u.lo, b33p, accB0);
                FMA2(accB1, w33.u.hi, b33p, accB1);
            }
            float2 rA0 = unpack2(accA0), rA1 = unpack2(accA1);
            float2 rB0 = unpack2(accB0), rB1 = unpack2(accB1);
            rmax[0] = fmaxf(rmax[0], fmaxf(rA0.x, rB0.x));
            rmax[1] = fmaxf(rmax[1], fmaxf(rA0.y, rB0.y));
            rmax[2] = fmaxf(rmax[2], fmaxf(rA1.x, rB1.x));
            rmax[3] = fmaxf(rmax[3], fmaxf(rA1.y, rB1.y));
        }
        __syncwarp();
    }
    #pragma unroll
    for (int j = 0; j < 4; j++) s.wmax[w][4 * lane + j] = rmax[j];
    __syncthreads();

    // ---------- row-max combine + cluster exchange ----------
    if (tid < LATENT) {
        float m = s.wmax[0][tid];
        #pragma unroll
        for (int ww = 1; ww < NWARP; ww++) m = fmaxf(m, s.wmax[ww][tid]);
        s.latloc[tid] = m;
        st_cluster_f32(peer_lat + (unsigned)tid * 4u, m);
    }
    cluster_sync_();

    if (tid < LATENT) {
        float m = fmaxf(s.latloc[tid], s.latpeer[tid]);
        s.vec[tid] = 1.f / (1.f + __expf(-m));
    }
    for (int j = tid; j < CELLS; j += NTHR) {
        float c = cell[(size_t)b * CELLS + j];
        s.vec[LATENT + j] = 1.f / (1.f + __expf(-c));
    }
    __syncthreads();

    const unsigned peer_h1 = mapa_peer(smem_u32(&s.h1[0]), prk);
    const unsigned peer_h2 = mapa_peer(smem_u32(&s.h2[0]), prk);
    const unsigned peer_p4 = mapa_peer(smem_u32(&s.partial4), prk);
    float* wflat = &s.wmax[0][0];

    // ---------- MLP L1: 640 -> 128, own 64 outs as 32 pairs, 16 k-parts ----------
    {
        const int o2 = tid & 31, part = tid >> 5;
        const int og2 = (own0 >> 1) + o2;
        const int k0 = part * 40;
        u64 acc0 = 0ull, acc1 = 0ull;
        #pragma unroll 4
        for (int k = k0; k < k0 + 40; k += 2) {
            u64 w0 = *reinterpret_cast<const u64*>(&W1[(size_t)k * 128 + 2 * og2]);
            u64 w1 = *reinterpret_cast<const u64*>(&W1[(size_t)(k + 1) * 128 + 2 * og2]);
            u64 v0 = pack2(s.vec[k], s.vec[k]);
            u64 v1 = pack2(s.vec[k + 1], s.vec[k + 1]);
            FMA2(acc0, w0, v0, acc0);
            FMA2(acc1, w1, v1, acc1);
        }
        float2 p0 = unpack2(acc0), p1 = unpack2(acc1);
        *reinterpret_cast<float2*>(&wflat[part * 64 + 2 * o2]) =
            make_float2(p0.x + p1.x, p0.y + p1.y);
    }
    __syncthreads();
    if (tid < 32) {
        float2 v = *reinterpret_cast<const float2*>(&wflat[2 * tid]);
        #pragma unroll
        for (int p = 1; p < 16; p++) {
            float2 t = *reinterpret_cast<const float2*>(&wflat[p * 64 + 2 * tid]);
            v.x += t.x; v.y += t.y;
        }
        const int og = own0 + 2 * tid;
        v.x = fmaxf(v.x + b1[og], 0.f);
        v.y = fmaxf(v.y + b1[og + 1], 0.f);
        *reinterpret_cast<float2*>(&s.h1[og]) = v;
        st_cluster_u64(peer_h1 + (unsigned)og * 4u, pack2(v.x, v.y));
    }
    cluster_sync_();

    // ---------- MLP L2: 128 -> 256, own 128 outs as 64 pairs, 8 k-parts ----------
    {
        const int o2 = tid & 63, part = tid >> 6;
        const int og2 = (int)rank * 64 + o2;
        const int k0 = part * 16;
        u64 acc0 = 0ull, acc1 = 0ull;
        #pragma unroll 4
        for (int k = k0; k < k0 + 16; k += 2) {
            u64 w0 = *reinterpret_cast<const u64*>(&W2[(size_t)k * 256 + 2 * og2]);
            u64 w1 = *reinterpret_cast<const u64*>(&W2[(size_t)(k + 1) * 256 + 2 * og2]);
            u64 v0 = pack2(s.h1[k], s.h1[k]);
            u64 v1 = pack2(s.h1[k + 1], s.h1[k + 1]);
            FMA2(acc0, w0, v0, acc0);
            FMA2(acc1, w1, v1, acc1);
        }
        float2 p0 = unpack2(acc0), p1 = unpack2(acc1);
        *reinterpret_cast<float2*>(&wflat[part * 128 + 2 * o2]) =
            make_float2(p0.x + p1.x, p0.y + p1.y);
    }
    __syncthreads();
    if (tid < 64) {
        float2 v = *reinterpret_cast<const float2*>(&wflat[2 * tid]);
        #pragma unroll
        for (int p = 1; p < 8; p++) {
            float2 t = *reinterpret_cast<const float2*>(&wflat[p * 128 + 2 * tid]);
            v.x += t.x; v.y += t.y;
        }
        const int og = (int)rank * 128 + 2 * tid;
        v.x = fmaxf(v.x + b2[og], 0.f);
        v.y = fmaxf(v.y + b2[og + 1], 0.f);
        *reinterpret_cast<float2*>(&s.h2[og]) = v;
        st_cluster_u64(peer_h2 + (unsigned)og * 4u, pack2(v.x, v.y));
    }
    cluster_sync_();

    // ---------- MLP L3: 256 -> 512, own 256 outs as 128 pairs, 4 k-parts ----------
    {
        const int o2 = tid & 127, part = tid >> 7;
        const int og2 = (int)rank * 128 + o2;
        const int k0 = part * 64;
        u64 acc0 = 0ull, acc1 = 0ull;
        #pragma unroll 4
        for (int k = k0; k < k0 + 64; k += 2) {
            u64 w0 = *reinterpret_cast<const u64*>(&W3[(size_t)k * 512 + 2 * og2]);
            u64 w1 = *reinterpret_cast<const u64*>(&W3[(size_t)(k + 1) * 512 + 2 * og2]);
            u64 v0 = pack2(s.h2[k], s.h2[k]);
            u64 v1 = pack2(s.h2[k + 1], s.h2[k + 1]);
            FMA2(acc0, w0, v0, acc0);
            FMA2(acc1, w1, v1, acc1);
        }
        float2 p0 = unpack2(acc0), p1 = unpack2(acc1);
        *reinterpret_cast<float2*>(&wflat[part * 256 + 2 * o2]) =
            make_float2(p0.x + p1.x, p0.y + p1.y);
    }
    __syncthreads();
    if (tid < 128) {
        float2 v = *reinterpret_cast<const float2*>(&wflat[2 * tid]);
        #pragma unroll
        for (int p = 1; p < 4; p++) {
            float2 t = *reinterpret_cast<const float2*>(&wflat[p * 256 + 2 * tid]);
            v.x += t.x; v.y += t.y;
        }
        const int og = (int)rank * 256 + 2 * tid;
        v.x = fmaxf(v.x + b3[og], 0.f);
        v.y = fmaxf(v.y + b3[og + 1], 0.f);
        *reinterpret_cast<float2*>(&s.h3own[2 * tid]) = v;
    }
    __syncthreads();

    // ---------- MLP L4: 512 -> 1 ----------
    {
        float acc = 0.f;
        if (tid < 256) acc = s.h3own[tid] * W4[(int)rank * 256 + tid];
        acc = warp_sum(acc);
        if (lane == 0) s.red[w] = acc;
    }
    __syncthreads();
    if (rank == 1 && tid == 0) {
        float acc = 0.f;
        #pragma unroll
        for (int ww = 0; ww < 8; ww++) acc += s.red[ww];
        st_cluster_f32(peer_p4, acc);
    }
    cluster_sync_();
    if (rank == 0 && tid == 0) {
        float acc = 0.f;
        #pragma unroll
        for (int ww = 0; ww < 8; ww++) acc += s.red[ww];
        out[b] = acc + s.partial4 + b4[0];
    }
}

} // namespace

extern "C" void kernel_launch(void* const* d_in, const int* in_sizes, int n_in,
                              void* d_out, int out_size) {
    (void)in_sizes; (void)n_in; (void)out_size;
    const float* xs   = (const float*)d_in[0];
    const int*   A    = (const int*)d_in[1];
    const float* cell = (const float*)d_in[2];
    const float* Wg   = (const float*)d_in[3];
    const float* bg   = (const float*)d_in[4];
    const float* attn = (const float*)d_in[5];
    const float* Wt   = (const float*)d_in[6];
    const float* bt   = (const float*)d_in[7];
    const float* Wf   = (const float*)d_in[8];
    const float* bf   = (const float*)d_in[9];
    const float* Wf2  = (const float*)d_in[10];
    const float* bf2  = (const float*)d_in[11];
    const float* W1   = (const float*)d_in[12];
    const float* b1   = (const float*)d_in[13];
    const float* W2   = (const float*)d_in[14];
    const float* b2   = (const float*)d_in[15];
    const float* W3   = (const float*)d_in[16];
    const float* b3   = (const float*)d_in[17];
    const float* W4   = (const float*)d_in[18];
    const float* b4   = (const float*)d_in[19];
    float* out = (float*)d_out;

    cudaFuncSetAttribute(disease_kernel,
                         cudaFuncAttributeMaxDynamicSharedMemorySize,
                         (int)sizeof(Smem));
    disease_kernel<<<128, NTHR, sizeof(Smem)>>>(
        xs, A, cell, Wg, bg, attn, Wt, bt, Wf, bf, Wf2, bf2,
        W1, b1, W2, b2, W3, b3, W4, b4, out);
}